// round 7
// baseline (speedup 1.0000x reference)
#include <cuda_runtime.h>
#include <cuda_bf16.h>
#include <cuda_fp16.h>
#include <math.h>
#include <stdint.h>

#define BSZ   2
#define SEQ   2048
#define EMB   2048
#define NH    16
#define DH    128
#define QKVN  ((NH + 2) * DH)   // 2304
#define MROWS (BSZ * SEQ)       // 4096
#define GK    2048               // inner K of both GEMMs

// ---------------- scratch (__device__ globals: allocation-free) ------------
__device__ __align__(128) __nv_bfloat16 g_xhi[(size_t)MROWS * EMB];
__device__ __align__(128) __nv_bfloat16 g_xlo[(size_t)MROWS * EMB];
__device__ __align__(128) __nv_bfloat16 g_wahi[(size_t)QKVN * EMB];
__device__ __align__(128) __nv_bfloat16 g_walo[(size_t)QKVN * EMB];
__device__ __align__(128) __nv_bfloat16 g_wohi[(size_t)EMB * EMB];
__device__ __align__(128) __nv_bfloat16 g_wolo[(size_t)EMB * EMB];
__device__ __align__(128) float         g_qkv[(size_t)MROWS * QKVN];
__device__ __align__(128) __nv_bfloat16 g_ahi[(size_t)MROWS * EMB];
__device__ __align__(128) __nv_bfloat16 g_alo[(size_t)MROWS * EMB];
// pre-converted K/V (split)
__device__ __align__(128) __nv_bfloat16 g_khi[(size_t)MROWS * DH];
__device__ __align__(128) __nv_bfloat16 g_klo[(size_t)MROWS * DH];
__device__ __align__(128) __half        g_vhi[(size_t)MROWS * DH];
__device__ __align__(128) __half        g_vlo[(size_t)MROWS * DH];

// ---------------- PTX helpers (sm_80-class only; no 'a' features) ----------
__device__ __forceinline__ uint32_t smem_u32(const void* p) {
    uint32_t a;
    asm("{ .reg .u64 t; cvta.to.shared.u64 t, %1; cvt.u32.u64 %0, t; }"
        : "=r"(a) : "l"(p));
    return a;
}
__device__ __forceinline__ void cp_async16(uint32_t dst, const void* src) {
    asm volatile("cp.async.cg.shared.global [%0], [%1], 16;"
                 :: "r"(dst), "l"(src) : "memory");
}
__device__ __forceinline__ void cp_commit() {
    asm volatile("cp.async.commit_group;" ::: "memory");
}
__device__ __forceinline__ void cp_wait0() {
    asm volatile("cp.async.wait_group 0;" ::: "memory");
}
__device__ __forceinline__ void ldsm4(uint32_t* r, uint32_t addr) {
    asm volatile("ldmatrix.sync.aligned.m8n8.x4.shared.b16 {%0,%1,%2,%3}, [%4];"
                 : "=r"(r[0]), "=r"(r[1]), "=r"(r[2]), "=r"(r[3]) : "r"(addr));
}
__device__ __forceinline__ void ldsm4t(uint32_t* r, uint32_t addr) {
    asm volatile("ldmatrix.sync.aligned.m8n8.x4.trans.shared.b16 {%0,%1,%2,%3}, [%4];"
                 : "=r"(r[0]), "=r"(r[1]), "=r"(r[2]), "=r"(r[3]) : "r"(addr));
}
__device__ __forceinline__ void ldsm2t(uint32_t* r, uint32_t addr) {
    asm volatile("ldmatrix.sync.aligned.m8n8.x2.trans.shared.b16 {%0,%1}, [%2];"
                 : "=r"(r[0]), "=r"(r[1]) : "r"(addr));
}
__device__ __forceinline__ void mma_bf16(float* c, const uint32_t* a,
                                         uint32_t b0, uint32_t b1) {
    asm volatile(
        "mma.sync.aligned.m16n8k16.row.col.f32.bf16.bf16.f32 "
        "{%0,%1,%2,%3}, {%4,%5,%6,%7}, {%8,%9}, {%0,%1,%2,%3};"
        : "+f"(c[0]), "+f"(c[1]), "+f"(c[2]), "+f"(c[3])
        : "r"(a[0]), "r"(a[1]), "r"(a[2]), "r"(a[3]), "r"(b0), "r"(b1));
}
__device__ __forceinline__ void mma_f16(float* c, uint32_t a0, uint32_t a1,
                                        uint32_t a2, uint32_t a3,
                                        uint32_t b0, uint32_t b1) {
    asm volatile(
        "mma.sync.aligned.m16n8k16.row.col.f32.f16.f16.f32 "
        "{%0,%1,%2,%3}, {%4,%5,%6,%7}, {%8,%9}, {%0,%1,%2,%3};"
        : "+f"(c[0]), "+f"(c[1]), "+f"(c[2]), "+f"(c[3])
        : "r"(a0), "r"(a1), "r"(a2), "r"(a3), "r"(b0), "r"(b1));
}
__device__ __forceinline__ uint32_t ex2_f16x2(float xhi, float xlo) {
    uint32_t h, r;
    asm("cvt.rn.f16x2.f32 %0, %1, %2;" : "=r"(h) : "f"(xhi), "f"(xlo));
    asm("ex2.approx.f16x2 %0, %1;" : "=r"(r) : "r"(h));
    return r;
}
__device__ __forceinline__ float ex2f(float x) {
    float r;
    asm("ex2.approx.f32 %0, %1;" : "=f"(r) : "f"(x));
    return r;
}
__device__ __forceinline__ uint32_t pbf2(float x, float y) {
    __nv_bfloat162 t(__float2bfloat16(x), __float2bfloat16(y));
    return *(uint32_t*)&t;
}

// ---------------------------------------------------------------------------
// split fp32 -> (hi, lo) bf16 elementwise
// ---------------------------------------------------------------------------
__global__ void __launch_bounds__(256) split_f32(const float* __restrict__ src,
                                                 __nv_bfloat16* __restrict__ hi,
                                                 __nv_bfloat16* __restrict__ lo,
                                                 int n4) {
    int i = blockIdx.x * blockDim.x + threadIdx.x;
    int stride = gridDim.x * blockDim.x;
    for (; i < n4; i += stride) {
        float4 v = ((const float4*)src)[i];
        __nv_bfloat16 h0 = __float2bfloat16(v.x), h1 = __float2bfloat16(v.y);
        __nv_bfloat16 h2 = __float2bfloat16(v.z), h3 = __float2bfloat16(v.w);
        __nv_bfloat16 l0 = __float2bfloat16(v.x - __bfloat162float(h0));
        __nv_bfloat16 l1 = __float2bfloat16(v.y - __bfloat162float(h1));
        __nv_bfloat16 l2 = __float2bfloat16(v.z - __bfloat162float(h2));
        __nv_bfloat16 l3 = __float2bfloat16(v.w - __bfloat162float(h3));
        ((__nv_bfloat162*)hi)[2 * i]     = __nv_bfloat162(h0, h1);
        ((__nv_bfloat162*)hi)[2 * i + 1] = __nv_bfloat162(h2, h3);
        ((__nv_bfloat162*)lo)[2 * i]     = __nv_bfloat162(l0, l1);
        ((__nv_bfloat162*)lo)[2 * i + 1] = __nv_bfloat162(l2, l3);
    }
}

// ---------------------------------------------------------------------------
// transpose + split: src [R][C] fp32 -> hi/lo [C][R] bf16
// ---------------------------------------------------------------------------
__global__ void __launch_bounds__(256) transpose_split(const float* __restrict__ src,
                                                       __nv_bfloat16* __restrict__ hi,
                                                       __nv_bfloat16* __restrict__ lo,
                                                       int R, int C) {
    __shared__ float t[32][33];
    int c0 = blockIdx.x * 32, r0 = blockIdx.y * 32;
    int tx = threadIdx.x & 31, ty = threadIdx.x >> 5;
#pragma unroll
    for (int i = 0; i < 32; i += 8)
        t[ty + i][tx] = src[(size_t)(r0 + ty + i) * C + c0 + tx];
    __syncthreads();
#pragma unroll
    for (int i = 0; i < 32; i += 8) {
        float v = t[tx][ty + i];
        __nv_bfloat16 h = __float2bfloat16(v);
        __nv_bfloat16 l = __float2bfloat16(v - __bfloat162float(h));
        size_t o = (size_t)(c0 + ty + i) * R + r0 + tx;
        hi[o] = h;
        lo[o] = l;
    }
}

// ---------------------------------------------------------------------------
// one-time K/V split conversion
// ---------------------------------------------------------------------------
__global__ void __launch_bounds__(256) convert_kv(const float* __restrict__ qkv,
                                                  __nv_bfloat16* __restrict__ khi,
                                                  __nv_bfloat16* __restrict__ klo,
                                                  __half* __restrict__ vhi,
                                                  __half* __restrict__ vlo) {
    int row = blockIdx.x * 2 + (threadIdx.x >> 7);
    int c = threadIdx.x & 127;
    const float* src = qkv + (size_t)row * QKVN;
    float k = src[EMB + c];
    float v = src[EMB + DH + c];
    __nv_bfloat16 kh = __float2bfloat16(k);
    khi[(size_t)row * DH + c] = kh;
    klo[(size_t)row * DH + c] = __float2bfloat16(k - __bfloat162float(kh));
    __half vh = __float2half_rn(v);
    vhi[(size_t)row * DH + c] = vh;
    vlo[(size_t)row * DH + c] = __float2half_rn(v - __half2float(vh));
}

// ---------------------------------------------------------------------------
// Split-bf16 GEMM via mma.sync: C[M,N] = (Ahi+Alo) @ (Bhi+Blo)^T
// CTA tile 128x256, 8 warps x (64x64), K chunk 32, 2-stage cp.async.
// ---------------------------------------------------------------------------
#define KCH     32
#define ROWB    80
#define ATILEB  (128 * ROWB)              // 10240
#define BTILEB  (256 * ROWB)              // 20480
#define OFF_AHI 0
#define OFF_ALO ATILEB
#define OFF_BHI (2 * ATILEB)
#define OFF_BLO (2 * ATILEB + BTILEB)
#define STAGEB  (2 * ATILEB + 2 * BTILEB) // 61440
#define GSMEM   (2 * STAGEB)              // 122880

__global__ void __launch_bounds__(256)
gemm_mma(const __nv_bfloat16* __restrict__ Ahi, const __nv_bfloat16* __restrict__ Alo,
         const __nv_bfloat16* __restrict__ Bhi, const __nv_bfloat16* __restrict__ Blo,
         float* __restrict__ C, int N) {
    extern __shared__ char smc[];
    const uint32_t sbase = smem_u32(smc);

    const int tid  = threadIdx.x;
    const int wid  = tid >> 5;
    const int lane = tid & 31;
    const int bm = blockIdx.y * 128;
    const int bn = blockIdx.x * 256;
    const int wm = (wid >> 2) * 64;    // 0 / 64
    const int wn = (wid & 3) * 64;     // 0..192

    // loaders: A rows via (tid>>1, half), B rows via tid (full 64B row)
    const int ar   = tid >> 1;
    const int half = tid & 1;
    const __nv_bfloat16* pAhi = Ahi + (size_t)(bm + ar) * GK + half * 16;
    const __nv_bfloat16* pAlo = Alo + (size_t)(bm + ar) * GK + half * 16;
    const __nv_bfloat16* pBhi = Bhi + (size_t)(bn + tid) * GK;
    const __nv_bfloat16* pBlo = Blo + (size_t)(bn + tid) * GK;
    const uint32_t adst = (uint32_t)(ar * ROWB + half * 32);
    const uint32_t bdst = (uint32_t)(tid * ROWB);

    float c[4][8][4];
#pragma unroll
    for (int mt = 0; mt < 4; mt++)
#pragma unroll
        for (int f = 0; f < 8; f++)
#pragma unroll
            for (int k = 0; k < 4; k++) c[mt][f][k] = 0.0f;

    const int NCH = GK / KCH;   // 64

    // prologue: chunk 0 -> stage 0
    {
        cp_async16(sbase + OFF_AHI + adst, pAhi);
        cp_async16(sbase + OFF_AHI + adst + 16, pAhi + 8);
        cp_async16(sbase + OFF_ALO + adst, pAlo);
        cp_async16(sbase + OFF_ALO + adst + 16, pAlo + 8);
#pragma unroll
        for (int j = 0; j < 4; j++) {
            cp_async16(sbase + OFF_BHI + bdst + j * 16, pBhi + j * 8);
            cp_async16(sbase + OFF_BLO + bdst + j * 16, pBlo + j * 8);
        }
        cp_commit();
    }

    for (int ch = 0; ch < NCH; ch++) {
        cp_wait0();
        __syncthreads();
        if (ch + 1 < NCH) {
            const uint32_t st2 = sbase + ((ch + 1) & 1) * STAGEB;
            const int k0 = (ch + 1) * KCH;
            cp_async16(st2 + OFF_AHI + adst, pAhi + k0);
            cp_async16(st2 + OFF_AHI + adst + 16, pAhi + k0 + 8);
            cp_async16(st2 + OFF_ALO + adst, pAlo + k0);
            cp_async16(st2 + OFF_ALO + adst + 16, pAlo + k0 + 8);
#pragma unroll
            for (int j = 0; j < 4; j++) {
                cp_async16(st2 + OFF_BHI + bdst + j * 16, pBhi + k0 + j * 8);
                cp_async16(st2 + OFF_BLO + bdst + j * 16, pBlo + k0 + j * 8);
            }
            cp_commit();
        }
        const uint32_t st = sbase + (ch & 1) * STAGEB;

#pragma unroll
        for (int ks = 0; ks < 2; ks++) {
            const uint32_t kcol = (uint32_t)(ks * 32 + (lane >> 4) * 16);
            uint32_t ah[4][4], al[4][4], bh[4][4], bl[4][4];
#pragma unroll
            for (int mt = 0; mt < 4; mt++) {
                uint32_t ra = st + (uint32_t)((wm + mt * 16 + (lane & 15)) * ROWB) + kcol;
                ldsm4(ah[mt], ra + OFF_AHI);
                ldsm4(al[mt], ra + OFF_ALO);
            }
#pragma unroll
            for (int g = 0; g < 4; g++) {
                uint32_t rb = st + (uint32_t)((wn + g * 16 + (lane & 15)) * ROWB) + kcol;
                ldsm4(bh[g], rb + OFF_BHI);
                ldsm4(bl[g], rb + OFF_BLO);
            }
            // pass 1: Ahi x Bhi (32 mma, distance 32)
#pragma unroll
            for (int mt = 0; mt < 4; mt++)
#pragma unroll
                for (int g = 0; g < 4; g++) {
                    mma_bf16(c[mt][2 * g],     ah[mt], bh[g][0], bh[g][2]);
                    mma_bf16(c[mt][2 * g + 1], ah[mt], bh[g][1], bh[g][3]);
                }
            // pass 2: Ahi x Blo
#pragma unroll
            for (int mt = 0; mt < 4; mt++)
#pragma unroll
                for (int g = 0; g < 4; g++) {
                    mma_bf16(c[mt][2 * g],     ah[mt], bl[g][0], bl[g][2]);
                    mma_bf16(c[mt][2 * g + 1], ah[mt], bl[g][1], bl[g][3]);
                }
            // pass 3: Alo x Bhi
#pragma unroll
            for (int mt = 0; mt < 4; mt++)
#pragma unroll
                for (int g = 0; g < 4; g++) {
                    mma_bf16(c[mt][2 * g],     al[mt], bh[g][0], bh[g][2]);
                    mma_bf16(c[mt][2 * g + 1], al[mt], bh[g][1], bh[g][3]);
                }
        }
    }

#pragma unroll
    for (int mt = 0; mt < 4; mt++)
#pragma unroll
        for (int f = 0; f < 8; f++) {
            int row = bm + wm + mt * 16 + (lane >> 2);
            int col = bn + wn + f * 8 + (lane & 3) * 2;
            *(float2*)&C[(size_t)row * N + col] =
                make_float2(c[mt][f][0], c[mt][f][1]);
            *(float2*)&C[(size_t)(row + 8) * N + col] =
                make_float2(c[mt][f][2], c[mt][f][3]);
        }
}

// ---------------------------------------------------------------------------
// Tensor-core flash MQA with pre-converted K/V streamed via cp.async.
// Pass-major mma ordering for longer RAW distance.
// ---------------------------------------------------------------------------
#define FROW    272
#define OFF_QHI 0
#define OFF_QLO (128 * FROW)
#define OFF_ST  (2 * 128 * FROW)
#define STAGEF  (4 * 64 * FROW)
#define FSMEM   (OFF_ST + 2 * STAGEF)

__device__ __forceinline__ void issue_kv_tile(
    uint32_t stbase, int lr, int lcb, size_t ge,
    const __nv_bfloat16* __restrict__ khi, const __nv_bfloat16* __restrict__ klo,
    const __half* __restrict__ vhi, const __half* __restrict__ vlo) {
    uint32_t d = stbase + (uint32_t)(lr * FROW + lcb);
    const char* pk = (const char*)(khi + ge);
    const char* pK = (const char*)(klo + ge);
    const char* pv = (const char*)(vhi + ge);
    const char* pV = (const char*)(vlo + ge);
#pragma unroll
    for (int jj = 0; jj < 4; jj++) {
        cp_async16(d + jj * 16, pk + jj * 16);
        cp_async16(d + 64 * FROW + jj * 16, pK + jj * 16);
        cp_async16(d + 128 * FROW + jj * 16, pv + jj * 16);
        cp_async16(d + 192 * FROW + jj * 16, pV + jj * 16);
    }
}

__global__ void __launch_bounds__(256, 1)
mqa_flash_mma(const float* __restrict__ qkv,
              const __nv_bfloat16* __restrict__ gkhi,
              const __nv_bfloat16* __restrict__ gklo,
              const __half* __restrict__ gvhi, const __half* __restrict__ gvlo,
              __nv_bfloat16* __restrict__ ahi, __nv_bfloat16* __restrict__ alo) {
    extern __shared__ char smf[];
    const uint32_t sb = smem_u32(smf);
    const int tid  = threadIdx.x;
    const int wid  = tid >> 5;
    const int lane = tid & 31;
    const int q0 = blockIdx.x * 128;
    const int h  = blockIdx.y;
    const int b  = blockIdx.z;
    const int wm = wid * 16;

    // ---- load Q tile -> split-bf16 smem, scale*log2e folded ----
    {
        const float sc = rsqrtf((float)DH) * 1.4426950408889634f;
        int row = tid >> 1, c0 = (tid & 1) * 64;
        const float* src = qkv + (size_t)(b * SEQ + q0 + row) * QKVN + h * DH + c0;
        char* dhi = smf + OFF_QHI + row * FROW + c0 * 2;
        char* dlo = smf + OFF_QLO + row * FROW + c0 * 2;
#pragma unroll
        for (int p = 0; p < 8; p++) {
            float4 a = *(const float4*)(src + p * 8);
            float4 d = *(const float4*)(src + p * 8 + 4);
            float v[8] = {a.x * sc, a.y * sc, a.z * sc, a.w * sc,
                          d.x * sc, d.y * sc, d.z * sc, d.w * sc};
            uint4 hh, ll;
            uint32_t* hp = (uint32_t*)&hh;
            uint32_t* lp = (uint32_t*)&ll;
#pragma unroll
            for (int j = 0; j < 4; j++) {
                float x = v[2 * j], y = v[2 * j + 1];
                float xh = __bfloat162float(__float2bfloat16(x));
                float yh = __bfloat162float(__float2bfloat16(y));
                hp[j] = pbf2(x, y);
                lp[j] = pbf2(x - xh, y - yh);
            }
            *(uint4*)(dhi + p * 16) = hh;
            *(uint4*)(dlo + p * 16) = ll;
        }
    }
    if (tid < 128) {
        int s = tid >> 6, row = tid & 63;
        char* vrow = smf + OFF_ST + s * STAGEF + 128 * FROW + row * FROW + 256;
        *(uint4*)vrow = make_uint4(0x00003C00u, 0u, 0u, 0u);
        *(uint4*)(vrow + 64 * FROW) = make_uint4(0u, 0u, 0u, 0u);
    }

    const int lr  = tid >> 2;
    const int lcb = (tid & 3) * 64;
    const size_t gebase = ((size_t)(b * SEQ + lr) << 7) + (lcb >> 1);

    float O[17][4];
#pragma unroll
    for (int f = 0; f < 17; f++)
#pragma unroll
        for (int j = 0; j < 4; j++) O[f][j] = 0.0f;
    float m0 = -1e30f, m1 = -1e30f;

    issue_kv_tile(sb + OFF_ST, lr, lcb, gebase, gkhi, gklo, gvhi, gvlo);
    cp_commit();

    const int NT = SEQ / 64;
    for (int t = 0; t < NT; t++) {
        cp_wait0();
        __syncthreads();
        if (t + 1 < NT) {
            issue_kv_tile(sb + OFF_ST + ((t + 1) & 1) * STAGEF, lr, lcb,
                          gebase + (size_t)(t + 1) * 64 * 128, gkhi, gklo, gvhi, gvlo);
            cp_commit();
        }
        const uint32_t stb = sb + OFF_ST + (t & 1) * STAGEF;

        // ---- QK^T: split-bf16 3-pass (log2 domain), pass-major ----
        float c[8][4];
#pragma unroll
        for (int nt = 0; nt < 8; nt++)
#pragma unroll
            for (int j = 0; j < 4; j++) c[nt][j] = 0.0f;

#pragma unroll
        for (int ks = 0; ks < 8; ks++) {
            const uint32_t kcol = (uint32_t)(ks * 32 + (lane >> 4) * 16);
            uint32_t ah[4], al[4], kh[4][4], kl[4][4];
            uint32_t qoff = sb + (uint32_t)((wm + (lane & 15)) * FROW) + kcol;
            ldsm4(ah, qoff + OFF_QHI);
            ldsm4(al, qoff + OFF_QLO);
#pragma unroll
            for (int g = 0; g < 4; g++) {
                uint32_t ko = stb + (uint32_t)((g * 16 + (lane & 15)) * FROW) + kcol;
                ldsm4(kh[g], ko);
                ldsm4(kl[g], ko + 64 * FROW);
            }
            // hh
#pragma unroll
            for (int g = 0; g < 4; g++) {
                mma_bf16(c[2 * g],     ah, kh[g][0], kh[g][2]);
                mma_bf16(c[2 * g + 1], ah, kh[g][1], kh[g][3]);
            }
            // hl
#pragma unroll
            for (int g = 0; g < 4; g++) {
                mma_bf16(c[2 * g],     ah, kl[g][0], kl[g][2]);
                mma_bf16(c[2 * g + 1], ah, kl[g][1], kl[g][3]);
            }
            // lh
#pragma unroll
            for (int g = 0; g < 4; g++) {
                mma_bf16(c[2 * g],     al, kh[g][0], kh[g][2]);
                mma_bf16(c[2 * g + 1], al, kh[g][1], kh[g][3]);
            }
        }

        // ---- online softmax (log2 domain), p in f16x2 ----
        float mt0 = -1e30f, mt1 = -1e30f;
#pragma unroll
        for (int nt = 0; nt < 8; nt++) {
            mt0 = fmaxf(mt0, fmaxf(c[nt][0], c[nt][1]));
            mt1 = fmaxf(mt1, fmaxf(c[nt][2], c[nt][3]));
        }
        mt0 = fmaxf(mt0, __shfl_xor_sync(0xffffffffu, mt0, 1));
        mt0 = fmaxf(mt0, __shfl_xor_sync(0xffffffffu, mt0, 2));
        mt1 = fmaxf(mt1, __shfl_xor_sync(0xffffffffu, mt1, 1));
        mt1 = fmaxf(mt1, __shfl_xor_sync(0xffffffffu, mt1, 2));
        float mn0 = fmaxf(m0, mt0), mn1 = fmaxf(m1, mt1);
        float corr0 = ex2f(m0 - mn0), corr1 = ex2f(m1 - mn1);
        m0 = mn0;
        m1 = mn1;
#pragma unroll
        for (int f = 0; f < 17; f++) {
            O[f][0] *= corr0; O[f][1] *= corr0;
            O[f][2] *= corr1; O[f][3] *= corr1;
        }
        uint32_t ph[8][2];
#pragma unroll
        for (int nt = 0; nt < 8; nt++) {
            ph[nt][0] = ex2_f16x2(c[nt][1] - mn0, c[nt][0] - mn0);
            ph[nt][1] = ex2_f16x2(c[nt][3] - mn1, c[nt][2] - mn1);
        }

        // ---- PV: pass-major (vh across all 16 O frags, then vl) ----
        const uint32_t vb = stb + 128 * FROW;
#pragma unroll
        for (int j = 0; j < 4; j++) {
            uint32_t a0 = ph[2 * j][0], a1 = ph[2 * j][1];
            uint32_t a2 = ph[2 * j + 1][0], a3 = ph[2 * j + 1][1];
            uint32_t vrow = vb + (uint32_t)((j * 16 + (lane & 15)) * FROW);
            const uint32_t ccol = (uint32_t)((lane >> 4) * 8) * 2;
            // vh pass: groups g=0..7 (16 cols each)
            uint32_t vfa[4][4];
#pragma unroll
            for (int g = 0; g < 4; g++) ldsm4t(vfa[g], vrow + g * 32 + ccol);
#pragma unroll
            for (int g = 0; g < 4; g++) {
                mma_f16(O[2 * g],     a0, a1, a2, a3, vfa[g][0], vfa[g][1]);
                mma_f16(O[2 * g + 1], a0, a1, a2, a3, vfa[g][2], vfa[g][3]);
            }
#pragma unroll
            for (int g = 0; g < 4; g++) ldsm4t(vfa[g], vrow + 128 + g * 32 + ccol);
#pragma unroll
            for (int g = 0; g < 4; g++) {
                mma_f16(O[8 + 2 * g],     a0, a1, a2, a3, vfa[g][0], vfa[g][1]);
                mma_f16(O[8 + 2 * g + 1], a0, a1, a2, a3, vfa[g][2], vfa[g][3]);
            }
            // vl pass
#pragma unroll
            for (int g = 0; g < 4; g++)
                ldsm4t(vfa[g], vrow + 64 * FROW + g * 32 + ccol);
#pragma unroll
            for (int g = 0; g < 4; g++) {
                mma_f16(O[2 * g],     a0, a1, a2, a3, vfa[g][0], vfa[g][1]);
                mma_f16(O[2 * g + 1], a0, a1, a2, a3, vfa[g][2], vfa[g][3]);
            }
#pragma unroll
            for (int g = 0; g < 4; g++)
                ldsm4t(vfa[g], vrow + 64 * FROW + 128 + g * 32 + ccol);
#pragma unroll
            for (int g = 0; g < 4; g++) {
                mma_f16(O[8 + 2 * g],     a0, a1, a2, a3, vfa[g][0], vfa[g][1]);
                mma_f16(O[8 + 2 * g + 1], a0, a1, a2, a3, vfa[g][2], vfa[g][3]);
            }
            // row-sum column
            uint32_t lh[2];
            ldsm2t(lh, vrow + 256);
            mma_f16(O[16], a0, a1, a2, a3, lh[0], lh[1]);
        }
    }

    // ---- epilogue: normalize, write split-bf16 attn ----
    float l0 = __shfl_sync(0xffffffffu, O[16][0], lane & 28);
    float l1 = __shfl_sync(0xffffffffu, O[16][2], lane & 28);
    float inv0 = 1.0f / l0, inv1 = 1.0f / l1;
    size_t base0 = (size_t)(b * SEQ + q0 + wm + (lane >> 2)) * EMB + h * DH +
                   2 * (lane & 3);
    size_t base1 = base0 + (size_t)8 * EMB;
#pragma unroll
    for (int nt = 0; nt < 16; nt++) {
        float v0 = O[nt][0] * inv0, v1 = O[nt][1] * inv0;
        float v2 = O[nt][2] * inv1, v3 = O[nt][3] * inv1;
        float h0 = __bfloat162float(__float2bfloat16(v0));
        float h1 = __bfloat162float(__float2bfloat16(v1));
        float h2 = __bfloat162float(__float2bfloat16(v2));
        float h3 = __bfloat162float(__float2bfloat16(v3));
        *(uint32_t*)(ahi + base0 + nt * 8) = pbf2(v0, v1);
        *(uint32_t*)(alo + base0 + nt * 8) = pbf2(v0 - h0, v1 - h1);
        *(uint32_t*)(ahi + base1 + nt * 8) = pbf2(v2, v3);
        *(uint32_t*)(alo + base1 + nt * 8) = pbf2(v2 - h2, v3 - h3);
    }
}

// ---------------------------------------------------------------------------
extern "C" void kernel_launch(void* const* d_in, const int* in_sizes, int n_in,
                              void* d_out, int out_size) {
    const float* x      = (const float*)d_in[0];
    const float* w_attn = (const float*)d_in[1];
    const float* w_out  = (const float*)d_in[2];
    float* out = (float*)d_out;

    __nv_bfloat16 *xhi, *xlo, *wahi, *walo, *wohi, *wolo, *ahi, *alo, *khi, *klo;
    __half *vhi, *vlo;
    float* qkv;
    cudaGetSymbolAddress((void**)&xhi, g_xhi);
    cudaGetSymbolAddress((void**)&xlo, g_xlo);
    cudaGetSymbolAddress((void**)&wahi, g_wahi);
    cudaGetSymbolAddress((void**)&walo, g_walo);
    cudaGetSymbolAddress((void**)&wohi, g_wohi);
    cudaGetSymbolAddress((void**)&wolo, g_wolo);
    cudaGetSymbolAddress((void**)&ahi, g_ahi);
    cudaGetSymbolAddress((void**)&alo, g_alo);
    cudaGetSymbolAddress((void**)&khi, g_khi);
    cudaGetSymbolAddress((void**)&klo, g_klo);
    cudaGetSymbolAddress((void**)&vhi, g_vhi);
    cudaGetSymbolAddress((void**)&vlo, g_vlo);
    cudaGetSymbolAddress((void**)&qkv, g_qkv);

    cudaFuncSetAttribute(gemm_mma, cudaFuncAttributeMaxDynamicSharedMemorySize,
                         GSMEM);
    cudaFuncSetAttribute(mqa_flash_mma, cudaFuncAttributeMaxDynamicSharedMemorySize,
                         FSMEM);

    // 1) convert inputs
    split_f32<<<512, 256>>>(x, xhi, xlo, MROWS * EMB / 4);
    transpose_split<<<dim3(QKVN / 32, EMB / 32), 256>>>(w_attn, wahi, walo, EMB, QKVN);
    transpose_split<<<dim3(EMB / 32, EMB / 32), 256>>>(w_out, wohi, wolo, EMB, EMB);

    // 2) qkv = x @ w_attn
    gemm_mma<<<dim3(QKVN / 256, MROWS / 128), 256, GSMEM>>>(
        xhi, xlo, wahi, walo, qkv, QKVN);

    // 3) one-time K/V split conversion
    convert_kv<<<MROWS / 2, 256>>>(qkv, khi, klo, vhi, vlo);

    // 4) tensor-core flash MQA -> split-bf16 attn
    mqa_flash_mma<<<dim3(SEQ / 128, NH, BSZ), 256, FSMEM>>>(
        qkv, khi, klo, vhi, vlo, ahi, alo);

    // 5) out = attn @ w_out
    gemm_mma<<<dim3(EMB / 256, MROWS / 128), 256, GSMEM>>>(
        ahi, alo, wohi, wolo, out, EMB);
}

// round 8
// speedup vs baseline: 1.3451x; 1.3451x over previous
#include <cuda_runtime.h>
#include <cuda_bf16.h>
#include <cuda_fp16.h>
#include <math.h>
#include <stdint.h>

#define BSZ   2
#define SEQ   2048
#define EMB   2048
#define NH    16
#define DH    128
#define QKVN  ((NH + 2) * DH)   // 2304
#define MROWS (BSZ * SEQ)       // 4096
#define GK    2048               // inner K of both GEMMs

// ---------------- scratch (__device__ globals: allocation-free) ------------
__device__ __align__(128) __half g_x16[(size_t)MROWS * EMB];
__device__ __align__(128) __half g_wahi[(size_t)QKVN * EMB];
__device__ __align__(128) __half g_walo[(size_t)QKVN * EMB];
__device__ __align__(128) __half g_wohi[(size_t)EMB * EMB];
__device__ __align__(128) __half g_wolo[(size_t)EMB * EMB];
__device__ __align__(128) float  g_qkv[(size_t)MROWS * QKVN];
__device__ __align__(128) __half g_a16[(size_t)MROWS * EMB];
// pre-converted K/V (split f16)
__device__ __align__(128) __half g_khi[(size_t)MROWS * DH];
__device__ __align__(128) __half g_klo[(size_t)MROWS * DH];
__device__ __align__(128) __half g_vhi[(size_t)MROWS * DH];
__device__ __align__(128) __half g_vlo[(size_t)MROWS * DH];

// ---------------- PTX helpers (sm_80-class only; no 'a' features) ----------
__device__ __forceinline__ uint32_t smem_u32(const void* p) {
    uint32_t a;
    asm("{ .reg .u64 t; cvta.to.shared.u64 t, %1; cvt.u32.u64 %0, t; }"
        : "=r"(a) : "l"(p));
    return a;
}
__device__ __forceinline__ void cp_async16(uint32_t dst, const void* src) {
    asm volatile("cp.async.cg.shared.global [%0], [%1], 16;"
                 :: "r"(dst), "l"(src) : "memory");
}
__device__ __forceinline__ void cp_commit() {
    asm volatile("cp.async.commit_group;" ::: "memory");
}
__device__ __forceinline__ void cp_wait1() {
    asm volatile("cp.async.wait_group 1;" ::: "memory");
}
__device__ __forceinline__ void cp_wait0() {
    asm volatile("cp.async.wait_group 0;" ::: "memory");
}
__device__ __forceinline__ void ldsm4(uint32_t* r, uint32_t addr) {
    asm volatile("ldmatrix.sync.aligned.m8n8.x4.shared.b16 {%0,%1,%2,%3}, [%4];"
                 : "=r"(r[0]), "=r"(r[1]), "=r"(r[2]), "=r"(r[3]) : "r"(addr));
}
__device__ __forceinline__ void ldsm4t(uint32_t* r, uint32_t addr) {
    asm volatile("ldmatrix.sync.aligned.m8n8.x4.trans.shared.b16 {%0,%1,%2,%3}, [%4];"
                 : "=r"(r[0]), "=r"(r[1]), "=r"(r[2]), "=r"(r[3]) : "r"(addr));
}
__device__ __forceinline__ void ldsm2t(uint32_t* r, uint32_t addr) {
    asm volatile("ldmatrix.sync.aligned.m8n8.x2.trans.shared.b16 {%0,%1}, [%2];"
                 : "=r"(r[0]), "=r"(r[1]) : "r"(addr));
}
__device__ __forceinline__ void mma_f16a(float* c, const uint32_t* a,
                                         uint32_t b0, uint32_t b1) {
    asm volatile(
        "mma.sync.aligned.m16n8k16.row.col.f32.f16.f16.f32 "
        "{%0,%1,%2,%3}, {%4,%5,%6,%7}, {%8,%9}, {%0,%1,%2,%3};"
        : "+f"(c[0]), "+f"(c[1]), "+f"(c[2]), "+f"(c[3])
        : "r"(a[0]), "r"(a[1]), "r"(a[2]), "r"(a[3]), "r"(b0), "r"(b1));
}
__device__ __forceinline__ void mma_f16(float* c, uint32_t a0, uint32_t a1,
                                        uint32_t a2, uint32_t a3,
                                        uint32_t b0, uint32_t b1) {
    asm volatile(
        "mma.sync.aligned.m16n8k16.row.col.f32.f16.f16.f32 "
        "{%0,%1,%2,%3}, {%4,%5,%6,%7}, {%8,%9}, {%0,%1,%2,%3};"
        : "+f"(c[0]), "+f"(c[1]), "+f"(c[2]), "+f"(c[3])
        : "r"(a0), "r"(a1), "r"(a2), "r"(a3), "r"(b0), "r"(b1));
}
__device__ __forceinline__ uint32_t ex2_f16x2(float xhi, float xlo) {
    uint32_t h, r;
    asm("cvt.rn.f16x2.f32 %0, %1, %2;" : "=r"(h) : "f"(xhi), "f"(xlo));
    asm("ex2.approx.f16x2 %0, %1;" : "=r"(r) : "r"(h));
    return r;
}
__device__ __forceinline__ float ex2f(float x) {
    float r;
    asm("ex2.approx.f32 %0, %1;" : "=f"(r) : "f"(x));
    return r;
}
__device__ __forceinline__ uint32_t phf2(float x, float y) {
    __half2 t(__float2half_rn(x), __float2half_rn(y));
    return *(uint32_t*)&t;
}

// ---------------------------------------------------------------------------
// fp32 -> f16 elementwise
// ---------------------------------------------------------------------------
__global__ void __launch_bounds__(256) conv_f16(const float* __restrict__ src,
                                                __half* __restrict__ dst, int n4) {
    int i = blockIdx.x * blockDim.x + threadIdx.x;
    int stride = gridDim.x * blockDim.x;
    for (; i < n4; i += stride) {
        float4 v = ((const float4*)src)[i];
        ((uint32_t*)dst)[2 * i]     = phf2(v.x, v.y);
        ((uint32_t*)dst)[2 * i + 1] = phf2(v.z, v.w);
    }
}

// ---------------------------------------------------------------------------
// transpose + split-f16: src [R][C] fp32 -> hi/lo [C][R] f16
// ---------------------------------------------------------------------------
__global__ void __launch_bounds__(256) transpose_split_f16(
    const float* __restrict__ src, __half* __restrict__ hi,
    __half* __restrict__ lo, int R, int C) {
    __shared__ float t[32][33];
    int c0 = blockIdx.x * 32, r0 = blockIdx.y * 32;
    int tx = threadIdx.x & 31, ty = threadIdx.x >> 5;
#pragma unroll
    for (int i = 0; i < 32; i += 8)
        t[ty + i][tx] = src[(size_t)(r0 + ty + i) * C + c0 + tx];
    __syncthreads();
#pragma unroll
    for (int i = 0; i < 32; i += 8) {
        float v = t[tx][ty + i];
        __half h = __float2half_rn(v);
        __half l = __float2half_rn(v - __half2float(h));
        size_t o = (size_t)(c0 + ty + i) * R + r0 + tx;
        hi[o] = h;
        lo[o] = l;
    }
}

// ---------------------------------------------------------------------------
// one-time K/V split-f16 conversion
// ---------------------------------------------------------------------------
__global__ void __launch_bounds__(256) convert_kv(const float* __restrict__ qkv,
                                                  __half* __restrict__ khi,
                                                  __half* __restrict__ klo,
                                                  __half* __restrict__ vhi,
                                                  __half* __restrict__ vlo) {
    int row = blockIdx.x * 2 + (threadIdx.x >> 7);
    int c = threadIdx.x & 127;
    const float* src = qkv + (size_t)row * QKVN;
    float k = src[EMB + c];
    float v = src[EMB + DH + c];
    __half kh = __float2half_rn(k);
    khi[(size_t)row * DH + c] = kh;
    klo[(size_t)row * DH + c] = __float2half_rn(k - __half2float(kh));
    __half vh = __float2half_rn(v);
    vhi[(size_t)row * DH + c] = vh;
    vlo[(size_t)row * DH + c] = __float2half_rn(v - __half2float(vh));
}

// ---------------------------------------------------------------------------
// Asymmetric split-f16 GEMM: C[M,N] = A16 @ (Bhi+Blo)^T   (2 mma passes)
// CTA 128x128, 8 warps x (64x32), K chunk 32, wait1 2-stage cp.async.
// ---------------------------------------------------------------------------
#define KCH     32
#define ROWB    80
#define TILEB   (128 * ROWB)          // 10240
#define OFF_A   0
#define OFF_BHI TILEB
#define OFF_BLO (2 * TILEB)
#define STAGEB  (3 * TILEB)           // 30720
#define GSMEM   (2 * STAGEB)          // 61440

__global__ void __launch_bounds__(256)
gemm_mma(const __half* __restrict__ A, const __half* __restrict__ Bhi,
         const __half* __restrict__ Blo, float* __restrict__ C, int N) {
    extern __shared__ char smc[];
    const uint32_t sbase = smem_u32(smc);

    const int tid  = threadIdx.x;
    const int wid  = tid >> 5;
    const int lane = tid & 31;
    const int bm = blockIdx.y * 128;
    const int bn = blockIdx.x * 128;
    const int wm = (wid >> 2) * 64;
    const int wn = (wid & 3) * 32;

    const int r  = tid >> 1;
    const int hf = tid & 1;
    const __half* pA  = A   + (size_t)(bm + r) * GK + hf * 16;
    const __half* pBh = Bhi + (size_t)(bn + r) * GK + hf * 16;
    const __half* pBl = Blo + (size_t)(bn + r) * GK + hf * 16;
    const uint32_t dst = (uint32_t)(r * ROWB + hf * 32);

    float c[4][4][4];
#pragma unroll
    for (int mt = 0; mt < 4; mt++)
#pragma unroll
        for (int nt = 0; nt < 4; nt++)
#pragma unroll
            for (int k = 0; k < 4; k++) c[mt][nt][k] = 0.0f;

    const int NCH = GK / KCH;

    // prologue: chunk 0 -> stage 0
    cp_async16(sbase + OFF_A + dst, pA);
    cp_async16(sbase + OFF_A + dst + 16, pA + 8);
    cp_async16(sbase + OFF_BHI + dst, pBh);
    cp_async16(sbase + OFF_BHI + dst + 16, pBh + 8);
    cp_async16(sbase + OFF_BLO + dst, pBl);
    cp_async16(sbase + OFF_BLO + dst + 16, pBl + 8);
    cp_commit();

    for (int ch = 0; ch < NCH; ch++) {
        const uint32_t st = sbase + (ch & 1) * STAGEB;
        if (ch + 1 < NCH) {
            const uint32_t st2 = sbase + ((ch + 1) & 1) * STAGEB;
            const int k0 = (ch + 1) * KCH;
            cp_async16(st2 + OFF_A + dst, pA + k0);
            cp_async16(st2 + OFF_A + dst + 16, pA + k0 + 8);
            cp_async16(st2 + OFF_BHI + dst, pBh + k0);
            cp_async16(st2 + OFF_BHI + dst + 16, pBh + k0 + 8);
            cp_async16(st2 + OFF_BLO + dst, pBl + k0);
            cp_async16(st2 + OFF_BLO + dst + 16, pBl + k0 + 8);
            cp_commit();
            cp_wait1();
        } else {
            cp_wait0();
        }
        __syncthreads();

#pragma unroll
        for (int ks = 0; ks < 2; ks++) {
            const uint32_t kcol = (uint32_t)(ks * 32 + (lane >> 4) * 16);
            uint32_t a[4][4];
#pragma unroll
            for (int mt = 0; mt < 4; mt++) {
                uint32_t ra = st + OFF_A +
                              (uint32_t)((wm + mt * 16 + (lane & 15)) * ROWB) + kcol;
                ldsm4(a[mt], ra);
            }
            uint32_t rb0 = st + OFF_BHI +
                           (uint32_t)((wn + (lane & 15)) * ROWB) + kcol;
            uint32_t rb1 = rb0 + 16 * ROWB;
            uint32_t bh0[4], bh1[4], bl0[4], bl1[4];
            ldsm4(bh0, rb0);
            ldsm4(bh1, rb1);
            ldsm4(bl0, rb0 + TILEB);
            ldsm4(bl1, rb1 + TILEB);

            // pass 1: A x Bhi
#pragma unroll
            for (int mt = 0; mt < 4; mt++) {
                mma_f16a(c[mt][0], a[mt], bh0[0], bh0[2]);
                mma_f16a(c[mt][1], a[mt], bh0[1], bh0[3]);
                mma_f16a(c[mt][2], a[mt], bh1[0], bh1[2]);
                mma_f16a(c[mt][3], a[mt], bh1[1], bh1[3]);
            }
            // pass 2: A x Blo
#pragma unroll
            for (int mt = 0; mt < 4; mt++) {
                mma_f16a(c[mt][0], a[mt], bl0[0], bl0[2]);
                mma_f16a(c[mt][1], a[mt], bl0[1], bl0[3]);
                mma_f16a(c[mt][2], a[mt], bl1[0], bl1[2]);
                mma_f16a(c[mt][3], a[mt], bl1[1], bl1[3]);
            }
        }
        __syncthreads();
    }

#pragma unroll
    for (int mt = 0; mt < 4; mt++)
#pragma unroll
        for (int nt = 0; nt < 4; nt++) {
            int row = bm + wm + mt * 16 + (lane >> 2);
            int col = bn + wn + nt * 8 + (lane & 3) * 2;
            *(float2*)&C[(size_t)row * N + col] =
                make_float2(c[mt][nt][0], c[mt][nt][1]);
            *(float2*)&C[(size_t)(row + 8) * N + col] =
                make_float2(c[mt][nt][2], c[mt][nt][3]);
        }
}

// ---------------------------------------------------------------------------
// Tensor-core flash MQA: Q f16 single x K split-f16 (2-pass QK),
// P f16 x V split-f16 (2-pass PV), row-sum via ones-column.
// ---------------------------------------------------------------------------
#define FROW    272
#define OFF_Q   0
#define OFF_ST  (128 * FROW)
#define STAGEF  (4 * 64 * FROW)
#define FSMEM   (OFF_ST + 2 * STAGEF)   // 174080

__device__ __forceinline__ void issue_kv_tile(
    uint32_t stbase, int lr, int lcb, size_t ge,
    const __half* __restrict__ khi, const __half* __restrict__ klo,
    const __half* __restrict__ vhi, const __half* __restrict__ vlo) {
    uint32_t d = stbase + (uint32_t)(lr * FROW + lcb);
    const char* pk = (const char*)(khi + ge);
    const char* pK = (const char*)(klo + ge);
    const char* pv = (const char*)(vhi + ge);
    const char* pV = (const char*)(vlo + ge);
#pragma unroll
    for (int jj = 0; jj < 4; jj++) {
        cp_async16(d + jj * 16, pk + jj * 16);
        cp_async16(d + 64 * FROW + jj * 16, pK + jj * 16);
        cp_async16(d + 128 * FROW + jj * 16, pv + jj * 16);
        cp_async16(d + 192 * FROW + jj * 16, pV + jj * 16);
    }
}

__global__ void __launch_bounds__(256, 1)
mqa_flash_mma(const float* __restrict__ qkv,
              const __half* __restrict__ gkhi, const __half* __restrict__ gklo,
              const __half* __restrict__ gvhi, const __half* __restrict__ gvlo,
              __half* __restrict__ a16) {
    extern __shared__ char smf[];
    const uint32_t sb = smem_u32(smf);
    const int tid  = threadIdx.x;
    const int wid  = tid >> 5;
    const int lane = tid & 31;
    const int q0 = blockIdx.x * 128;
    const int h  = blockIdx.y;
    const int b  = blockIdx.z;
    const int wm = wid * 16;

    // ---- load Q tile -> f16 smem, scale*log2e folded ----
    {
        const float sc = rsqrtf((float)DH) * 1.4426950408889634f;
        int row = tid >> 1, c0 = (tid & 1) * 64;
        const float* src = qkv + (size_t)(b * SEQ + q0 + row) * QKVN + h * DH + c0;
        char* dq = smf + OFF_Q + row * FROW + c0 * 2;
#pragma unroll
        for (int p = 0; p < 8; p++) {
            float4 a = *(const float4*)(src + p * 8);
            float4 d = *(const float4*)(src + p * 8 + 4);
            uint4 qq;
            uint32_t* qp = (uint32_t*)&qq;
            qp[0] = phf2(a.x * sc, a.y * sc);
            qp[1] = phf2(a.z * sc, a.w * sc);
            qp[2] = phf2(d.x * sc, d.y * sc);
            qp[3] = phf2(d.z * sc, d.w * sc);
            *(uint4*)(dq + p * 16) = qq;
        }
    }
    if (tid < 128) {
        int s = tid >> 6, row = tid & 63;
        char* vrow = smf + OFF_ST + s * STAGEF + 128 * FROW + row * FROW + 256;
        *(uint4*)vrow = make_uint4(0x00003C00u, 0u, 0u, 0u);
        *(uint4*)(vrow + 64 * FROW) = make_uint4(0u, 0u, 0u, 0u);
    }

    const int lr  = tid >> 2;
    const int lcb = (tid & 3) * 64;
    const size_t gebase = ((size_t)(b * SEQ + lr) << 7) + (lcb >> 1);

    float O[17][4];
#pragma unroll
    for (int f = 0; f < 17; f++)
#pragma unroll
        for (int j = 0; j < 4; j++) O[f][j] = 0.0f;
    float m0 = -1e30f, m1 = -1e30f;

    issue_kv_tile(sb + OFF_ST, lr, lcb, gebase, gkhi, gklo, gvhi, gvlo);
    cp_commit();

    const int NT = SEQ / 64;
    for (int t = 0; t < NT; t++) {
        cp_wait0();
        __syncthreads();
        if (t + 1 < NT) {
            issue_kv_tile(sb + OFF_ST + ((t + 1) & 1) * STAGEF, lr, lcb,
                          gebase + (size_t)(t + 1) * 64 * 128, gkhi, gklo, gvhi, gvlo);
            cp_commit();
        }
        const uint32_t stb = sb + OFF_ST + (t & 1) * STAGEF;

        // ---- QK^T: Q f16 x (Khi + Klo), 2 passes, log2 domain ----
        float c[8][4];
#pragma unroll
        for (int nt = 0; nt < 8; nt++)
#pragma unroll
            for (int j = 0; j < 4; j++) c[nt][j] = 0.0f;

#pragma unroll
        for (int ks = 0; ks < 8; ks++) {
            const uint32_t kcol = (uint32_t)(ks * 32 + (lane >> 4) * 16);
            uint32_t aq[4], kh[4][4], kl[4][4];
            ldsm4(aq, sb + OFF_Q + (uint32_t)((wm + (lane & 15)) * FROW) + kcol);
#pragma unroll
            for (int g = 0; g < 4; g++) {
                uint32_t ko = stb + (uint32_t)((g * 16 + (lane & 15)) * FROW) + kcol;
                ldsm4(kh[g], ko);
                ldsm4(kl[g], ko + 64 * FROW);
            }
#pragma unroll
            for (int g = 0; g < 4; g++) {
                mma_f16a(c[2 * g],     aq, kh[g][0], kh[g][2]);
                mma_f16a(c[2 * g + 1], aq, kh[g][1], kh[g][3]);
            }
#pragma unroll
            for (int g = 0; g < 4; g++) {
                mma_f16a(c[2 * g],     aq, kl[g][0], kl[g][2]);
                mma_f16a(c[2 * g + 1], aq, kl[g][1], kl[g][3]);
            }
        }

        // ---- online softmax (log2 domain), p in f16x2 ----
        float mt0 = -1e30f, mt1 = -1e30f;
#pragma unroll
        for (int nt = 0; nt < 8; nt++) {
            mt0 = fmaxf(mt0, fmaxf(c[nt][0], c[nt][1]));
            mt1 = fmaxf(mt1, fmaxf(c[nt][2], c[nt][3]));
        }
        mt0 = fmaxf(mt0, __shfl_xor_sync(0xffffffffu, mt0, 1));
        mt0 = fmaxf(mt0, __shfl_xor_sync(0xffffffffu, mt0, 2));
        mt1 = fmaxf(mt1, __shfl_xor_sync(0xffffffffu, mt1, 1));
        mt1 = fmaxf(mt1, __shfl_xor_sync(0xffffffffu, mt1, 2));
        float mn0 = fmaxf(m0, mt0), mn1 = fmaxf(m1, mt1);
        float corr0 = ex2f(m0 - mn0), corr1 = ex2f(m1 - mn1);
        m0 = mn0;
        m1 = mn1;
#pragma unroll
        for (int f = 0; f < 17; f++) {
            O[f][0] *= corr0; O[f][1] *= corr0;
            O[f][2] *= corr1; O[f][3] *= corr1;
        }
        uint32_t ph[8][2];
#pragma unroll
        for (int nt = 0; nt < 8; nt++) {
            ph[nt][0] = ex2_f16x2(c[nt][1] - mn0, c[nt][0] - mn0);
            ph[nt][1] = ex2_f16x2(c[nt][3] - mn1, c[nt][2] - mn1);
        }

        // ---- PV: pass-major (vh all 16 O frags, then vl) ----
        const uint32_t vb = stb + 128 * FROW;
#pragma unroll
        for (int j = 0; j < 4; j++) {
            uint32_t a0 = ph[2 * j][0], a1 = ph[2 * j][1];
            uint32_t a2 = ph[2 * j + 1][0], a3 = ph[2 * j + 1][1];
            uint32_t vrow = vb + (uint32_t)((j * 16 + (lane & 15)) * FROW);
            const uint32_t ccol = (uint32_t)((lane >> 4) * 8) * 2;
            uint32_t vfa[4][4];
#pragma unroll
            for (int g = 0; g < 4; g++) ldsm4t(vfa[g], vrow + g * 32 + ccol);
#pragma unroll
            for (int g = 0; g < 4; g++) {
                mma_f16(O[2 * g],     a0, a1, a2, a3, vfa[g][0], vfa[g][1]);
                mma_f16(O[2 * g + 1], a0, a1, a2, a3, vfa[g][2], vfa[g][3]);
            }
#pragma unroll
            for (int g = 0; g < 4; g++) ldsm4t(vfa[g], vrow + 128 + g * 32 + ccol);
#pragma unroll
            for (int g = 0; g < 4; g++) {
                mma_f16(O[8 + 2 * g],     a0, a1, a2, a3, vfa[g][0], vfa[g][1]);
                mma_f16(O[8 + 2 * g + 1], a0, a1, a2, a3, vfa[g][2], vfa[g][3]);
            }
#pragma unroll
            for (int g = 0; g < 4; g++)
                ldsm4t(vfa[g], vrow + 64 * FROW + g * 32 + ccol);
#pragma unroll
            for (int g = 0; g < 4; g++) {
                mma_f16(O[2 * g],     a0, a1, a2, a3, vfa[g][0], vfa[g][1]);
                mma_f16(O[2 * g + 1], a0, a1, a2, a3, vfa[g][2], vfa[g][3]);
            }
#pragma unroll
            for (int g = 0; g < 4; g++)
                ldsm4t(vfa[g], vrow + 64 * FROW + 128 + g * 32 + ccol);
#pragma unroll
            for (int g = 0; g < 4; g++) {
                mma_f16(O[8 + 2 * g],     a0, a1, a2, a3, vfa[g][0], vfa[g][1]);
                mma_f16(O[8 + 2 * g + 1], a0, a1, a2, a3, vfa[g][2], vfa[g][3]);
            }
            uint32_t lh[2];
            ldsm2t(lh, vrow + 256);
            mma_f16(O[16], a0, a1, a2, a3, lh[0], lh[1]);
        }
    }

    // ---- epilogue: normalize, write f16 attn ----
    float l0 = __shfl_sync(0xffffffffu, O[16][0], lane & 28);
    float l1 = __shfl_sync(0xffffffffu, O[16][2], lane & 28);
    float inv0 = 1.0f / l0, inv1 = 1.0f / l1;
    size_t base0 = (size_t)(b * SEQ + q0 + wm + (lane >> 2)) * EMB + h * DH +
                   2 * (lane & 3);
    size_t base1 = base0 + (size_t)8 * EMB;
#pragma unroll
    for (int nt = 0; nt < 16; nt++) {
        *(uint32_t*)(a16 + base0 + nt * 8) = phf2(O[nt][0] * inv0, O[nt][1] * inv0);
        *(uint32_t*)(a16 + base1 + nt * 8) = phf2(O[nt][2] * inv1, O[nt][3] * inv1);
    }
}

// ---------------------------------------------------------------------------
extern "C" void kernel_launch(void* const* d_in, const int* in_sizes, int n_in,
                              void* d_out, int out_size) {
    const float* x      = (const float*)d_in[0];
    const float* w_attn = (const float*)d_in[1];
    const float* w_out  = (const float*)d_in[2];
    float* out = (float*)d_out;

    __half *x16, *wahi, *walo, *wohi, *wolo, *a16, *khi, *klo, *vhi, *vlo;
    float* qkv;
    cudaGetSymbolAddress((void**)&x16, g_x16);
    cudaGetSymbolAddress((void**)&wahi, g_wahi);
    cudaGetSymbolAddress((void**)&walo, g_walo);
    cudaGetSymbolAddress((void**)&wohi, g_wohi);
    cudaGetSymbolAddress((void**)&wolo, g_wolo);
    cudaGetSymbolAddress((void**)&a16, g_a16);
    cudaGetSymbolAddress((void**)&khi, g_khi);
    cudaGetSymbolAddress((void**)&klo, g_klo);
    cudaGetSymbolAddress((void**)&vhi, g_vhi);
    cudaGetSymbolAddress((void**)&vlo, g_vlo);
    cudaGetSymbolAddress((void**)&qkv, g_qkv);

    cudaFuncSetAttribute(gemm_mma, cudaFuncAttributeMaxDynamicSharedMemorySize,
                         GSMEM);
    cudaFuncSetAttribute(mqa_flash_mma, cudaFuncAttributeMaxDynamicSharedMemorySize,
                         FSMEM);

    // 1) convert inputs
    conv_f16<<<512, 256>>>(x, x16, MROWS * EMB / 4);
    transpose_split_f16<<<dim3(QKVN / 32, EMB / 32), 256>>>(w_attn, wahi, walo,
                                                            EMB, QKVN);
    transpose_split_f16<<<dim3(EMB / 32, EMB / 32), 256>>>(w_out, wohi, wolo,
                                                           EMB, EMB);

    // 2) qkv = x @ w_attn  (2-pass asymmetric split-f16)
    gemm_mma<<<dim3(QKVN / 128, MROWS / 128), 256, GSMEM>>>(
        x16, wahi, walo, qkv, QKVN);

    // 3) one-time K/V split-f16 conversion
    convert_kv<<<MROWS / 2, 256>>>(qkv, khi, klo, vhi, vlo);

    // 4) tensor-core flash MQA -> f16 attn
    mqa_flash_mma<<<dim3(SEQ / 128, NH, BSZ), 256, FSMEM>>>(
        qkv, khi, klo, vhi, vlo, a16);

    // 5) out = attn @ w_out  (2-pass asymmetric split-f16)
    gemm_mma<<<dim3(EMB / 128, MROWS / 128), 256, GSMEM>>>(
        a16, wohi, wolo, out, EMB);
}

// round 9
// speedup vs baseline: 1.5107x; 1.1231x over previous
#include <cuda_runtime.h>
#include <cuda_bf16.h>
#include <cuda_fp16.h>
#include <math.h>
#include <stdint.h>

#define BSZ   2
#define SEQ   2048
#define EMB   2048
#define NH    16
#define DH    128
#define QKVN  ((NH + 2) * DH)   // 2304
#define MROWS (BSZ * SEQ)       // 4096
#define GK    2048               // inner K of both GEMMs

// ---------------- scratch (__device__ globals: allocation-free) ------------
__device__ __align__(128) __half g_x16[(size_t)MROWS * EMB];
__device__ __align__(128) __half g_wahi[(size_t)QKVN * EMB];
__device__ __align__(128) __half g_walo[(size_t)QKVN * EMB];
__device__ __align__(128) __half g_wohi[(size_t)EMB * EMB];
__device__ __align__(128) __half g_wolo[(size_t)EMB * EMB];
__device__ __align__(128) float  g_qkv[(size_t)MROWS * QKVN];
__device__ __align__(128) __half g_a16[(size_t)MROWS * EMB];
// pre-converted K (split f16) and V (single f16)
__device__ __align__(128) __half g_khi[(size_t)MROWS * DH];
__device__ __align__(128) __half g_klo[(size_t)MROWS * DH];
__device__ __align__(128) __half g_v16[(size_t)MROWS * DH];

// ---------------- PTX helpers (sm_80-class only; no 'a' features) ----------
__device__ __forceinline__ uint32_t smem_u32(const void* p) {
    uint32_t a;
    asm("{ .reg .u64 t; cvta.to.shared.u64 t, %1; cvt.u32.u64 %0, t; }"
        : "=r"(a) : "l"(p));
    return a;
}
__device__ __forceinline__ void cp_async16(uint32_t dst, const void* src) {
    asm volatile("cp.async.cg.shared.global [%0], [%1], 16;"
                 :: "r"(dst), "l"(src) : "memory");
}
__device__ __forceinline__ void cp_commit() {
    asm volatile("cp.async.commit_group;" ::: "memory");
}
__device__ __forceinline__ void cp_wait1() {
    asm volatile("cp.async.wait_group 1;" ::: "memory");
}
__device__ __forceinline__ void cp_wait0() {
    asm volatile("cp.async.wait_group 0;" ::: "memory");
}
__device__ __forceinline__ void ldsm4(uint32_t* r, uint32_t addr) {
    asm volatile("ldmatrix.sync.aligned.m8n8.x4.shared.b16 {%0,%1,%2,%3}, [%4];"
                 : "=r"(r[0]), "=r"(r[1]), "=r"(r[2]), "=r"(r[3]) : "r"(addr));
}
__device__ __forceinline__ void ldsm4t(uint32_t* r, uint32_t addr) {
    asm volatile("ldmatrix.sync.aligned.m8n8.x4.trans.shared.b16 {%0,%1,%2,%3}, [%4];"
                 : "=r"(r[0]), "=r"(r[1]), "=r"(r[2]), "=r"(r[3]) : "r"(addr));
}
__device__ __forceinline__ void ldsm2t(uint32_t* r, uint32_t addr) {
    asm volatile("ldmatrix.sync.aligned.m8n8.x2.trans.shared.b16 {%0,%1}, [%2];"
                 : "=r"(r[0]), "=r"(r[1]) : "r"(addr));
}
__device__ __forceinline__ void mma_f16a(float* c, const uint32_t* a,
                                         uint32_t b0, uint32_t b1) {
    asm volatile(
        "mma.sync.aligned.m16n8k16.row.col.f32.f16.f16.f32 "
        "{%0,%1,%2,%3}, {%4,%5,%6,%7}, {%8,%9}, {%0,%1,%2,%3};"
        : "+f"(c[0]), "+f"(c[1]), "+f"(c[2]), "+f"(c[3])
        : "r"(a[0]), "r"(a[1]), "r"(a[2]), "r"(a[3]), "r"(b0), "r"(b1));
}
__device__ __forceinline__ void mma_f16(float* c, uint32_t a0, uint32_t a1,
                                        uint32_t a2, uint32_t a3,
                                        uint32_t b0, uint32_t b1) {
    asm volatile(
        "mma.sync.aligned.m16n8k16.row.col.f32.f16.f16.f32 "
        "{%0,%1,%2,%3}, {%4,%5,%6,%7}, {%8,%9}, {%0,%1,%2,%3};"
        : "+f"(c[0]), "+f"(c[1]), "+f"(c[2]), "+f"(c[3])
        : "r"(a0), "r"(a1), "r"(a2), "r"(a3), "r"(b0), "r"(b1));
}
__device__ __forceinline__ uint32_t ex2_f16x2(float xhi, float xlo) {
    uint32_t h, r;
    asm("cvt.rn.f16x2.f32 %0, %1, %2;" : "=r"(h) : "f"(xhi), "f"(xlo));
    asm("ex2.approx.f16x2 %0, %1;" : "=r"(r) : "r"(h));
    return r;
}
__device__ __forceinline__ float ex2f(float x) {
    float r;
    asm("ex2.approx.f32 %0, %1;" : "=f"(r) : "f"(x));
    return r;
}
__device__ __forceinline__ uint32_t phf2(float x, float y) {
    __half2 t(__float2half_rn(x), __float2half_rn(y));
    return *(uint32_t*)&t;
}

// ---------------------------------------------------------------------------
// fp32 -> f16 elementwise
// ---------------------------------------------------------------------------
__global__ void __launch_bounds__(256) conv_f16(const float* __restrict__ src,
                                                __half* __restrict__ dst, int n4) {
    int i = blockIdx.x * blockDim.x + threadIdx.x;
    int stride = gridDim.x * blockDim.x;
    for (; i < n4; i += stride) {
        float4 v = ((const float4*)src)[i];
        ((uint32_t*)dst)[2 * i]     = phf2(v.x, v.y);
        ((uint32_t*)dst)[2 * i + 1] = phf2(v.z, v.w);
    }
}

// ---------------------------------------------------------------------------
// transpose + split-f16: src [R][C] fp32 -> hi/lo [C][R] f16
// ---------------------------------------------------------------------------
__global__ void __launch_bounds__(256) transpose_split_f16(
    const float* __restrict__ src, __half* __restrict__ hi,
    __half* __restrict__ lo, int R, int C) {
    __shared__ float t[32][33];
    int c0 = blockIdx.x * 32, r0 = blockIdx.y * 32;
    int tx = threadIdx.x & 31, ty = threadIdx.x >> 5;
#pragma unroll
    for (int i = 0; i < 32; i += 8)
        t[ty + i][tx] = src[(size_t)(r0 + ty + i) * C + c0 + tx];
    __syncthreads();
#pragma unroll
    for (int i = 0; i < 32; i += 8) {
        float v = t[tx][ty + i];
        __half h = __float2half_rn(v);
        __half l = __float2half_rn(v - __half2float(h));
        size_t o = (size_t)(c0 + ty + i) * R + r0 + tx;
        hi[o] = h;
        lo[o] = l;
    }
}

// ---------------------------------------------------------------------------
// one-time K split + V single conversion
// ---------------------------------------------------------------------------
__global__ void __launch_bounds__(256) convert_kv(const float* __restrict__ qkv,
                                                  __half* __restrict__ khi,
                                                  __half* __restrict__ klo,
                                                  __half* __restrict__ v16) {
    int row = blockIdx.x * 2 + (threadIdx.x >> 7);
    int c = threadIdx.x & 127;
    const float* src = qkv + (size_t)row * QKVN;
    float k = src[EMB + c];
    float v = src[EMB + DH + c];
    __half kh = __float2half_rn(k);
    khi[(size_t)row * DH + c] = kh;
    klo[(size_t)row * DH + c] = __float2half_rn(k - __half2float(kh));
    v16[(size_t)row * DH + c] = __float2half_rn(v);
}

// ---------------------------------------------------------------------------
// Asymmetric split-f16 GEMM: C[M,N] = A16 @ (Bhi+Blo)^T   (2 mma passes)
// CTA 128x128, 8 warps x (64x32), K chunk 32.
// 3-stage cp.async pipeline, issue offset 2, wait_group 1, single barrier:
// each load group gets ~2 chunk-computes of latency cover.
// ---------------------------------------------------------------------------
#define KCH     32
#define ROWB    80
#define TILEB   (128 * ROWB)          // 10240
#define OFF_A   0
#define OFF_BHI TILEB
#define OFF_BLO (2 * TILEB)
#define STAGEB  (3 * TILEB)           // 30720
#define GSMEM   (3 * STAGEB)          // 92160

__global__ void __launch_bounds__(256)
gemm_mma(const __half* __restrict__ A, const __half* __restrict__ Bhi,
         const __half* __restrict__ Blo, float* __restrict__ C, int N) {
    extern __shared__ char smc[];
    const uint32_t sbase = smem_u32(smc);

    const int tid  = threadIdx.x;
    const int wid  = tid >> 5;
    const int lane = tid & 31;
    const int bm = blockIdx.y * 128;
    const int bn = blockIdx.x * 128;
    const int wm = (wid >> 2) * 64;
    const int wn = (wid & 3) * 32;

    const int r  = tid >> 1;
    const int hf = tid & 1;
    const __half* pA  = A   + (size_t)(bm + r) * GK + hf * 16;
    const __half* pBh = Bhi + (size_t)(bn + r) * GK + hf * 16;
    const __half* pBl = Blo + (size_t)(bn + r) * GK + hf * 16;
    const uint32_t dst = (uint32_t)(r * ROWB + hf * 32);

    float c[4][4][4];
#pragma unroll
    for (int mt = 0; mt < 4; mt++)
#pragma unroll
        for (int nt = 0; nt < 4; nt++)
#pragma unroll
            for (int k = 0; k < 4; k++) c[mt][nt][k] = 0.0f;

    const int NCH = GK / KCH;   // 64

    // prologue: chunks 0 and 1 -> stages 0 and 1
#pragma unroll
    for (int p = 0; p < 2; p++) {
        const uint32_t st = sbase + p * STAGEB;
        const int k0 = p * KCH;
        cp_async16(st + OFF_A + dst, pA + k0);
        cp_async16(st + OFF_A + dst + 16, pA + k0 + 8);
        cp_async16(st + OFF_BHI + dst, pBh + k0);
        cp_async16(st + OFF_BHI + dst + 16, pBh + k0 + 8);
        cp_async16(st + OFF_BLO + dst, pBl + k0);
        cp_async16(st + OFF_BLO + dst + 16, pBl + k0 + 8);
        cp_commit();
    }

    int sidx = 0;   // stage of current chunk
    for (int ch = 0; ch < NCH; ch++) {
        if (ch + 1 < NCH) cp_wait1(); else cp_wait0();
        __syncthreads();
        if (ch + 2 < NCH) {
            int s2 = sidx + 2; if (s2 >= 3) s2 -= 3;
            const uint32_t st2 = sbase + s2 * STAGEB;
            const int k0 = (ch + 2) * KCH;
            cp_async16(st2 + OFF_A + dst, pA + k0);
            cp_async16(st2 + OFF_A + dst + 16, pA + k0 + 8);
            cp_async16(st2 + OFF_BHI + dst, pBh + k0);
            cp_async16(st2 + OFF_BHI + dst + 16, pBh + k0 + 8);
            cp_async16(st2 + OFF_BLO + dst, pBl + k0);
            cp_async16(st2 + OFF_BLO + dst + 16, pBl + k0 + 8);
            cp_commit();
        }
        const uint32_t st = sbase + sidx * STAGEB;

#pragma unroll
        for (int ks = 0; ks < 2; ks++) {
            const uint32_t kcol = (uint32_t)(ks * 32 + (lane >> 4) * 16);
            uint32_t a[4][4];
#pragma unroll
            for (int mt = 0; mt < 4; mt++) {
                uint32_t ra = st + OFF_A +
                              (uint32_t)((wm + mt * 16 + (lane & 15)) * ROWB) + kcol;
                ldsm4(a[mt], ra);
            }
            uint32_t rb0 = st + OFF_BHI +
                           (uint32_t)((wn + (lane & 15)) * ROWB) + kcol;
            uint32_t rb1 = rb0 + 16 * ROWB;
            uint32_t bh0[4], bh1[4], bl0[4], bl1[4];
            ldsm4(bh0, rb0);
            ldsm4(bh1, rb1);
            ldsm4(bl0, rb0 + TILEB);
            ldsm4(bl1, rb1 + TILEB);

            // pass 1: A x Bhi
#pragma unroll
            for (int mt = 0; mt < 4; mt++) {
                mma_f16a(c[mt][0], a[mt], bh0[0], bh0[2]);
                mma_f16a(c[mt][1], a[mt], bh0[1], bh0[3]);
                mma_f16a(c[mt][2], a[mt], bh1[0], bh1[2]);
                mma_f16a(c[mt][3], a[mt], bh1[1], bh1[3]);
            }
            // pass 2: A x Blo
#pragma unroll
            for (int mt = 0; mt < 4; mt++) {
                mma_f16a(c[mt][0], a[mt], bl0[0], bl0[2]);
                mma_f16a(c[mt][1], a[mt], bl0[1], bl0[3]);
                mma_f16a(c[mt][2], a[mt], bl1[0], bl1[2]);
                mma_f16a(c[mt][3], a[mt], bl1[1], bl1[3]);
            }
        }
        sidx = (sidx + 1 == 3) ? 0 : sidx + 1;
    }

#pragma unroll
    for (int mt = 0; mt < 4; mt++)
#pragma unroll
        for (int nt = 0; nt < 4; nt++) {
            int row = bm + wm + mt * 16 + (lane >> 2);
            int col = bn + wn + nt * 8 + (lane & 3) * 2;
            *(float2*)&C[(size_t)row * N + col] =
                make_float2(c[mt][nt][0], c[mt][nt][1]);
            *(float2*)&C[(size_t)(row + 8) * N + col] =
                make_float2(c[mt][nt][2], c[mt][nt][3]);
        }
}

// ---------------------------------------------------------------------------
// Tensor-core flash MQA: Q f16 x K split-f16 (2-pass QK),
// P f16 x V single f16 (1-pass PV), row-sum via ones-column.
// ---------------------------------------------------------------------------
#define FROW    272
#define OFF_Q   0
#define OFF_ST  (128 * FROW)
#define STAGEF  (3 * 64 * FROW)         // Khi Klo V = 52224
#define FSMEM   (OFF_ST + 2 * STAGEF)   // 139264

__device__ __forceinline__ void issue_kv_tile(
    uint32_t stbase, int lr, int lcb, size_t ge,
    const __half* __restrict__ khi, const __half* __restrict__ klo,
    const __half* __restrict__ v16) {
    uint32_t d = stbase + (uint32_t)(lr * FROW + lcb);
    const char* pk = (const char*)(khi + ge);
    const char* pK = (const char*)(klo + ge);
    const char* pv = (const char*)(v16 + ge);
#pragma unroll
    for (int jj = 0; jj < 4; jj++) {
        cp_async16(d + jj * 16, pk + jj * 16);
        cp_async16(d + 64 * FROW + jj * 16, pK + jj * 16);
        cp_async16(d + 128 * FROW + jj * 16, pv + jj * 16);
    }
}

__global__ void __launch_bounds__(256, 1)
mqa_flash_mma(const float* __restrict__ qkv,
              const __half* __restrict__ gkhi, const __half* __restrict__ gklo,
              const __half* __restrict__ gv16, __half* __restrict__ a16) {
    extern __shared__ char smf[];
    const uint32_t sb = smem_u32(smf);
    const int tid  = threadIdx.x;
    const int wid  = tid >> 5;
    const int lane = tid & 31;
    const int q0 = blockIdx.x * 128;
    const int h  = blockIdx.y;
    const int b  = blockIdx.z;
    const int wm = wid * 16;

    // ---- load Q tile -> f16 smem, scale*log2e folded ----
    {
        const float sc = rsqrtf((float)DH) * 1.4426950408889634f;
        int row = tid >> 1, c0 = (tid & 1) * 64;
        const float* src = qkv + (size_t)(b * SEQ + q0 + row) * QKVN + h * DH + c0;
        char* dq = smf + OFF_Q + row * FROW + c0 * 2;
#pragma unroll
        for (int p = 0; p < 8; p++) {
            float4 a = *(const float4*)(src + p * 8);
            float4 d = *(const float4*)(src + p * 8 + 4);
            uint4 qq;
            uint32_t* qp = (uint32_t*)&qq;
            qp[0] = phf2(a.x * sc, a.y * sc);
            qp[1] = phf2(a.z * sc, a.w * sc);
            qp[2] = phf2(d.x * sc, d.y * sc);
            qp[3] = phf2(d.z * sc, d.w * sc);
            *(uint4*)(dq + p * 16) = qq;
        }
    }
    // ones column (V col 128) in both stages, written once
    if (tid < 128) {
        int s = tid >> 6, row = tid & 63;
        char* vrow = smf + OFF_ST + s * STAGEF + 128 * FROW + row * FROW + 256;
        *(uint4*)vrow = make_uint4(0x00003C00u, 0u, 0u, 0u);
    }

    const int lr  = tid >> 2;
    const int lcb = (tid & 3) * 64;
    const size_t gebase = ((size_t)(b * SEQ + lr) << 7) + (lcb >> 1);

    float O[17][4];
#pragma unroll
    for (int f = 0; f < 17; f++)
#pragma unroll
        for (int j = 0; j < 4; j++) O[f][j] = 0.0f;
    float m0 = -1e30f, m1 = -1e30f;

    issue_kv_tile(sb + OFF_ST, lr, lcb, gebase, gkhi, gklo, gv16);
    cp_commit();

    const int NT = SEQ / 64;
    for (int t = 0; t < NT; t++) {
        cp_wait0();
        __syncthreads();
        if (t + 1 < NT) {
            issue_kv_tile(sb + OFF_ST + ((t + 1) & 1) * STAGEF, lr, lcb,
                          gebase + (size_t)(t + 1) * 64 * 128, gkhi, gklo, gv16);
            cp_commit();
        }
        const uint32_t stb = sb + OFF_ST + (t & 1) * STAGEF;

        // ---- QK^T: Q f16 x (Khi + Klo), 2 passes, log2 domain ----
        float c[8][4];
#pragma unroll
        for (int nt = 0; nt < 8; nt++)
#pragma unroll
            for (int j = 0; j < 4; j++) c[nt][j] = 0.0f;

#pragma unroll
        for (int ks = 0; ks < 8; ks++) {
            const uint32_t kcol = (uint32_t)(ks * 32 + (lane >> 4) * 16);
            uint32_t aq[4], kh[4][4], kl[4][4];
            ldsm4(aq, sb + OFF_Q + (uint32_t)((wm + (lane & 15)) * FROW) + kcol);
#pragma unroll
            for (int g = 0; g < 4; g++) {
                uint32_t ko = stb + (uint32_t)((g * 16 + (lane & 15)) * FROW) + kcol;
                ldsm4(kh[g], ko);
                ldsm4(kl[g], ko + 64 * FROW);
            }
#pragma unroll
            for (int g = 0; g < 4; g++) {
                mma_f16a(c[2 * g],     aq, kh[g][0], kh[g][2]);
                mma_f16a(c[2 * g + 1], aq, kh[g][1], kh[g][3]);
            }
#pragma unroll
            for (int g = 0; g < 4; g++) {
                mma_f16a(c[2 * g],     aq, kl[g][0], kl[g][2]);
                mma_f16a(c[2 * g + 1], aq, kl[g][1], kl[g][3]);
            }
        }

        // ---- online softmax (log2 domain), p in f16x2 ----
        float mt0 = -1e30f, mt1 = -1e30f;
#pragma unroll
        for (int nt = 0; nt < 8; nt++) {
            mt0 = fmaxf(mt0, fmaxf(c[nt][0], c[nt][1]));
            mt1 = fmaxf(mt1, fmaxf(c[nt][2], c[nt][3]));
        }
        mt0 = fmaxf(mt0, __shfl_xor_sync(0xffffffffu, mt0, 1));
        mt0 = fmaxf(mt0, __shfl_xor_sync(0xffffffffu, mt0, 2));
        mt1 = fmaxf(mt1, __shfl_xor_sync(0xffffffffu, mt1, 1));
        mt1 = fmaxf(mt1, __shfl_xor_sync(0xffffffffu, mt1, 2));
        float mn0 = fmaxf(m0, mt0), mn1 = fmaxf(m1, mt1);
        float corr0 = ex2f(m0 - mn0), corr1 = ex2f(m1 - mn1);
        m0 = mn0;
        m1 = mn1;
#pragma unroll
        for (int f = 0; f < 17; f++) {
            O[f][0] *= corr0; O[f][1] *= corr0;
            O[f][2] *= corr1; O[f][3] *= corr1;
        }
        uint32_t ph[8][2];
#pragma unroll
        for (int nt = 0; nt < 8; nt++) {
            ph[nt][0] = ex2_f16x2(c[nt][1] - mn0, c[nt][0] - mn0);
            ph[nt][1] = ex2_f16x2(c[nt][3] - mn1, c[nt][2] - mn1);
        }

        // ---- PV: P f16 x V single f16; col 128 = row sum ----
        const uint32_t vb = stb + 128 * FROW;
#pragma unroll
        for (int j = 0; j < 4; j++) {
            uint32_t a0 = ph[2 * j][0], a1 = ph[2 * j][1];
            uint32_t a2 = ph[2 * j + 1][0], a3 = ph[2 * j + 1][1];
            uint32_t vrow = vb + (uint32_t)((j * 16 + (lane & 15)) * FROW);
            const uint32_t ccol = (uint32_t)((lane >> 4) * 8) * 2;
            uint32_t vfa[4][4];
#pragma unroll
            for (int g = 0; g < 4; g++) ldsm4t(vfa[g], vrow + g * 32 + ccol);
#pragma unroll
            for (int g = 0; g < 4; g++) {
                mma_f16(O[2 * g],     a0, a1, a2, a3, vfa[g][0], vfa[g][1]);
                mma_f16(O[2 * g + 1], a0, a1, a2, a3, vfa[g][2], vfa[g][3]);
            }
#pragma unroll
            for (int g = 0; g < 4; g++) ldsm4t(vfa[g], vrow + 128 + g * 32 + ccol);
#pragma unroll
            for (int g = 0; g < 4; g++) {
                mma_f16(O[8 + 2 * g],     a0, a1, a2, a3, vfa[g][0], vfa[g][1]);
                mma_f16(O[8 + 2 * g + 1], a0, a1, a2, a3, vfa[g][2], vfa[g][3]);
            }
            uint32_t lh[2];
            ldsm2t(lh, vrow + 256);
            mma_f16(O[16], a0, a1, a2, a3, lh[0], lh[1]);
        }
    }

    // ---- epilogue: normalize, write f16 attn ----
    float l0 = __shfl_sync(0xffffffffu, O[16][0], lane & 28);
    float l1 = __shfl_sync(0xffffffffu, O[16][2], lane & 28);
    float inv0 = 1.0f / l0, inv1 = 1.0f / l1;
    size_t base0 = (size_t)(b * SEQ + q0 + wm + (lane >> 2)) * EMB + h * DH +
                   2 * (lane & 3);
    size_t base1 = base0 + (size_t)8 * EMB;
#pragma unroll
    for (int nt = 0; nt < 16; nt++) {
        *(uint32_t*)(a16 + base0 + nt * 8) = phf2(O[nt][0] * inv0, O[nt][1] * inv0);
        *(uint32_t*)(a16 + base1 + nt * 8) = phf2(O[nt][2] * inv1, O[nt][3] * inv1);
    }
}

// ---------------------------------------------------------------------------
extern "C" void kernel_launch(void* const* d_in, const int* in_sizes, int n_in,
                              void* d_out, int out_size) {
    const float* x      = (const float*)d_in[0];
    const float* w_attn = (const float*)d_in[1];
    const float* w_out  = (const float*)d_in[2];
    float* out = (float*)d_out;

    __half *x16, *wahi, *walo, *wohi, *wolo, *a16, *khi, *klo, *v16;
    float* qkv;
    cudaGetSymbolAddress((void**)&x16, g_x16);
    cudaGetSymbolAddress((void**)&wahi, g_wahi);
    cudaGetSymbolAddress((void**)&walo, g_walo);
    cudaGetSymbolAddress((void**)&wohi, g_wohi);
    cudaGetSymbolAddress((void**)&wolo, g_wolo);
    cudaGetSymbolAddress((void**)&a16, g_a16);
    cudaGetSymbolAddress((void**)&khi, g_khi);
    cudaGetSymbolAddress((void**)&klo, g_klo);
    cudaGetSymbolAddress((void**)&v16, g_v16);
    cudaGetSymbolAddress((void**)&qkv, g_qkv);

    cudaFuncSetAttribute(gemm_mma, cudaFuncAttributeMaxDynamicSharedMemorySize,
                         GSMEM);
    cudaFuncSetAttribute(mqa_flash_mma, cudaFuncAttributeMaxDynamicSharedMemorySize,
                         FSMEM);

    // 1) convert inputs
    conv_f16<<<512, 256>>>(x, x16, MROWS * EMB / 4);
    transpose_split_f16<<<dim3(QKVN / 32, EMB / 32), 256>>>(w_attn, wahi, walo,
                                                            EMB, QKVN);
    transpose_split_f16<<<dim3(EMB / 32, EMB / 32), 256>>>(w_out, wohi, wolo,
                                                           EMB, EMB);

    // 2) qkv = x @ w_attn  (2-pass asymmetric split-f16, 3-stage pipeline)
    gemm_mma<<<dim3(QKVN / 128, MROWS / 128), 256, GSMEM>>>(
        x16, wahi, walo, qkv, QKVN);

    // 3) one-time K split / V single conversion
    convert_kv<<<MROWS / 2, 256>>>(qkv, khi, klo, v16);

    // 4) tensor-core flash MQA -> f16 attn
    mqa_flash_mma<<<dim3(SEQ / 128, NH, BSZ), 256, FSMEM>>>(
        qkv, khi, klo, v16, a16);

    // 5) out = attn @ w_out  (2-pass asymmetric split-f16, 3-stage pipeline)
    gemm_mma<<<dim3(EMB / 128, MROWS / 128), 256, GSMEM>>>(
        a16, wohi, wolo, out, EMB);
}

// round 10
// speedup vs baseline: 1.5193x; 1.0057x over previous
#include <cuda_runtime.h>
#include <cuda_bf16.h>
#include <cuda_fp16.h>
#include <math.h>
#include <stdint.h>

#define BSZ   2
#define SEQ   2048
#define EMB   2048
#define NH    16
#define DH    128
#define QKVN  ((NH + 2) * DH)   // 2304
#define MROWS (BSZ * SEQ)       // 4096
#define GK    2048               // inner K of both GEMMs

// ---------------- scratch (__device__ globals: allocation-free) ------------
__device__ __align__(128) __half g_x16[(size_t)MROWS * EMB];
__device__ __align__(128) __half g_wahi[(size_t)QKVN * EMB];
__device__ __align__(128) __half g_walo[(size_t)QKVN * EMB];
__device__ __align__(128) __half g_wohi[(size_t)EMB * EMB];
__device__ __align__(128) __half g_wolo[(size_t)EMB * EMB];
__device__ __align__(128) __half g_q16[(size_t)MROWS * EMB];   // pre-scaled q
__device__ __align__(128) __half g_a16[(size_t)MROWS * EMB];
__device__ __align__(128) __half g_khi[(size_t)MROWS * DH];
__device__ __align__(128) __half g_klo[(size_t)MROWS * DH];
__device__ __align__(128) __half g_v16[(size_t)MROWS * DH];

// ---------------- PTX helpers (sm_80-class only; no 'a' features) ----------
__device__ __forceinline__ uint32_t smem_u32(const void* p) {
    uint32_t a;
    asm("{ .reg .u64 t; cvta.to.shared.u64 t, %1; cvt.u32.u64 %0, t; }"
        : "=r"(a) : "l"(p));
    return a;
}
__device__ __forceinline__ void cp_async16(uint32_t dst, const void* src) {
    asm volatile("cp.async.cg.shared.global [%0], [%1], 16;"
                 :: "r"(dst), "l"(src) : "memory");
}
__device__ __forceinline__ void cp_commit() {
    asm volatile("cp.async.commit_group;" ::: "memory");
}
__device__ __forceinline__ void cp_wait1() {
    asm volatile("cp.async.wait_group 1;" ::: "memory");
}
__device__ __forceinline__ void cp_wait0() {
    asm volatile("cp.async.wait_group 0;" ::: "memory");
}
__device__ __forceinline__ void ldsm4(uint32_t* r, uint32_t addr) {
    asm volatile("ldmatrix.sync.aligned.m8n8.x4.shared.b16 {%0,%1,%2,%3}, [%4];"
                 : "=r"(r[0]), "=r"(r[1]), "=r"(r[2]), "=r"(r[3]) : "r"(addr));
}
__device__ __forceinline__ void ldsm4t(uint32_t* r, uint32_t addr) {
    asm volatile("ldmatrix.sync.aligned.m8n8.x4.trans.shared.b16 {%0,%1,%2,%3}, [%4];"
                 : "=r"(r[0]), "=r"(r[1]), "=r"(r[2]), "=r"(r[3]) : "r"(addr));
}
__device__ __forceinline__ void ldsm2t(uint32_t* r, uint32_t addr) {
    asm volatile("ldmatrix.sync.aligned.m8n8.x2.trans.shared.b16 {%0,%1}, [%2];"
                 : "=r"(r[0]), "=r"(r[1]) : "r"(addr));
}
__device__ __forceinline__ void mma_f16a(float* c, const uint32_t* a,
                                         uint32_t b0, uint32_t b1) {
    asm volatile(
        "mma.sync.aligned.m16n8k16.row.col.f32.f16.f16.f32 "
        "{%0,%1,%2,%3}, {%4,%5,%6,%7}, {%8,%9}, {%0,%1,%2,%3};"
        : "+f"(c[0]), "+f"(c[1]), "+f"(c[2]), "+f"(c[3])
        : "r"(a[0]), "r"(a[1]), "r"(a[2]), "r"(a[3]), "r"(b0), "r"(b1));
}
__device__ __forceinline__ void mma_f16(float* c, uint32_t a0, uint32_t a1,
                                        uint32_t a2, uint32_t a3,
                                        uint32_t b0, uint32_t b1) {
    asm volatile(
        "mma.sync.aligned.m16n8k16.row.col.f32.f16.f16.f32 "
        "{%0,%1,%2,%3}, {%4,%5,%6,%7}, {%8,%9}, {%0,%1,%2,%3};"
        : "+f"(c[0]), "+f"(c[1]), "+f"(c[2]), "+f"(c[3])
        : "r"(a0), "r"(a1), "r"(a2), "r"(a3), "r"(b0), "r"(b1));
}
__device__ __forceinline__ uint32_t ex2_f16x2(float xhi, float xlo) {
    uint32_t h, r;
    asm("cvt.rn.f16x2.f32 %0, %1, %2;" : "=r"(h) : "f"(xhi), "f"(xlo));
    asm("ex2.approx.f16x2 %0, %1;" : "=r"(r) : "r"(h));
    return r;
}
__device__ __forceinline__ float ex2f(float x) {
    float r;
    asm("ex2.approx.f32 %0, %1;" : "=f"(r) : "f"(x));
    return r;
}
__device__ __forceinline__ uint32_t phf2(float x, float y) {
    __half2 t(__float2half_rn(x), __float2half_rn(y));
    return *(uint32_t*)&t;
}

// ---------------------------------------------------------------------------
// fp32 -> f16 elementwise
// ---------------------------------------------------------------------------
__global__ void __launch_bounds__(256) conv_f16(const float* __restrict__ src,
                                                __half* __restrict__ dst, int n4) {
    int i = blockIdx.x * blockDim.x + threadIdx.x;
    int stride = gridDim.x * blockDim.x;
    for (; i < n4; i += stride) {
        float4 v = ((const float4*)src)[i];
        ((uint32_t*)dst)[2 * i]     = phf2(v.x, v.y);
        ((uint32_t*)dst)[2 * i + 1] = phf2(v.z, v.w);
    }
}

// ---------------------------------------------------------------------------
// transpose + split-f16: src [R][C] fp32 -> hi/lo [C][R] f16
// ---------------------------------------------------------------------------
__global__ void __launch_bounds__(256) transpose_split_f16(
    const float* __restrict__ src, __half* __restrict__ hi,
    __half* __restrict__ lo, int R, int C) {
    __shared__ float t[32][33];
    int c0 = blockIdx.x * 32, r0 = blockIdx.y * 32;
    int tx = threadIdx.x & 31, ty = threadIdx.x >> 5;
#pragma unroll
    for (int i = 0; i < 32; i += 8)
        t[ty + i][tx] = src[(size_t)(r0 + ty + i) * C + c0 + tx];
    __syncthreads();
#pragma unroll
    for (int i = 0; i < 32; i += 8) {
        float v = t[tx][ty + i];
        __half h = __float2half_rn(v);
        __half l = __float2half_rn(v - __half2float(h));
        size_t o = (size_t)(c0 + ty + i) * R + r0 + tx;
        hi[o] = h;
        lo[o] = l;
    }
}

// ---------------------------------------------------------------------------
// Asymmetric split-f16 GEMM, 2 mma passes, 3-stage cp.async pipeline.
// MODE 0: C = fp32 out.  MODE 1: fused qkv epilogue -> q16 (scaled) / khi,klo / v16.
// ---------------------------------------------------------------------------
#define KCH     32
#define ROWB    80
#define TILEB   (128 * ROWB)          // 10240
#define OFF_A   0
#define OFF_BHI TILEB
#define OFF_BLO (2 * TILEB)
#define STAGEB  (3 * TILEB)           // 30720
#define GSMEM   (3 * STAGEB)          // 92160

template <int MODE>
__global__ void __launch_bounds__(256)
gemm_mma(const __half* __restrict__ A, const __half* __restrict__ Bhi,
         const __half* __restrict__ Blo, float* __restrict__ C,
         __half* __restrict__ q16, __half* __restrict__ khi,
         __half* __restrict__ klo, __half* __restrict__ v16, int N) {
    extern __shared__ char smc[];
    const uint32_t sbase = smem_u32(smc);

    const int tid  = threadIdx.x;
    const int wid  = tid >> 5;
    const int lane = tid & 31;
    const int bm = blockIdx.y * 128;
    const int bn = blockIdx.x * 128;
    const int wm = (wid >> 2) * 64;
    const int wn = (wid & 3) * 32;

    const int r  = tid >> 1;
    const int hf = tid & 1;
    const __half* pA  = A   + (size_t)(bm + r) * GK + hf * 16;
    const __half* pBh = Bhi + (size_t)(bn + r) * GK + hf * 16;
    const __half* pBl = Blo + (size_t)(bn + r) * GK + hf * 16;
    const uint32_t dst = (uint32_t)(r * ROWB + hf * 32);

    float c[4][4][4];
#pragma unroll
    for (int mt = 0; mt < 4; mt++)
#pragma unroll
        for (int nt = 0; nt < 4; nt++)
#pragma unroll
            for (int k = 0; k < 4; k++) c[mt][nt][k] = 0.0f;

    const int NCH = GK / KCH;   // 64

    // prologue: chunks 0 and 1 -> stages 0 and 1
#pragma unroll
    for (int p = 0; p < 2; p++) {
        const uint32_t st = sbase + p * STAGEB;
        const int k0 = p * KCH;
        cp_async16(st + OFF_A + dst, pA + k0);
        cp_async16(st + OFF_A + dst + 16, pA + k0 + 8);
        cp_async16(st + OFF_BHI + dst, pBh + k0);
        cp_async16(st + OFF_BHI + dst + 16, pBh + k0 + 8);
        cp_async16(st + OFF_BLO + dst, pBl + k0);
        cp_async16(st + OFF_BLO + dst + 16, pBl + k0 + 8);
        cp_commit();
    }

    int sidx = 0;
    for (int ch = 0; ch < NCH; ch++) {
        if (ch + 1 < NCH) cp_wait1(); else cp_wait0();
        __syncthreads();
        if (ch + 2 < NCH) {
            int s2 = sidx + 2; if (s2 >= 3) s2 -= 3;
            const uint32_t st2 = sbase + s2 * STAGEB;
            const int k0 = (ch + 2) * KCH;
            cp_async16(st2 + OFF_A + dst, pA + k0);
            cp_async16(st2 + OFF_A + dst + 16, pA + k0 + 8);
            cp_async16(st2 + OFF_BHI + dst, pBh + k0);
            cp_async16(st2 + OFF_BHI + dst + 16, pBh + k0 + 8);
            cp_async16(st2 + OFF_BLO + dst, pBl + k0);
            cp_async16(st2 + OFF_BLO + dst + 16, pBl + k0 + 8);
            cp_commit();
        }
        const uint32_t st = sbase + sidx * STAGEB;

#pragma unroll
        for (int ks = 0; ks < 2; ks++) {
            const uint32_t kcol = (uint32_t)(ks * 32 + (lane >> 4) * 16);
            uint32_t a[4][4];
#pragma unroll
            for (int mt = 0; mt < 4; mt++) {
                uint32_t ra = st + OFF_A +
                              (uint32_t)((wm + mt * 16 + (lane & 15)) * ROWB) + kcol;
                ldsm4(a[mt], ra);
            }
            uint32_t rb0 = st + OFF_BHI +
                           (uint32_t)((wn + (lane & 15)) * ROWB) + kcol;
            uint32_t rb1 = rb0 + 16 * ROWB;
            uint32_t bh0[4], bh1[4], bl0[4], bl1[4];
            ldsm4(bh0, rb0);
            ldsm4(bh1, rb1);
            ldsm4(bl0, rb0 + TILEB);
            ldsm4(bl1, rb1 + TILEB);

#pragma unroll
            for (int mt = 0; mt < 4; mt++) {
                mma_f16a(c[mt][0], a[mt], bh0[0], bh0[2]);
                mma_f16a(c[mt][1], a[mt], bh0[1], bh0[3]);
                mma_f16a(c[mt][2], a[mt], bh1[0], bh1[2]);
                mma_f16a(c[mt][3], a[mt], bh1[1], bh1[3]);
            }
#pragma unroll
            for (int mt = 0; mt < 4; mt++) {
                mma_f16a(c[mt][0], a[mt], bl0[0], bl0[2]);
                mma_f16a(c[mt][1], a[mt], bl0[1], bl0[3]);
                mma_f16a(c[mt][2], a[mt], bl1[0], bl1[2]);
                mma_f16a(c[mt][3], a[mt], bl1[1], bl1[3]);
            }
        }
        sidx = (sidx + 1 == 3) ? 0 : sidx + 1;
    }

    // ---- epilogue ----
    if (MODE == 0) {
#pragma unroll
        for (int mt = 0; mt < 4; mt++)
#pragma unroll
            for (int nt = 0; nt < 4; nt++) {
                int row = bm + wm + mt * 16 + (lane >> 2);
                int col = bn + wn + nt * 8 + (lane & 3) * 2;
                *(float2*)&C[(size_t)row * N + col] =
                    make_float2(c[mt][nt][0], c[mt][nt][1]);
                *(float2*)&C[(size_t)(row + 8) * N + col] =
                    make_float2(c[mt][nt][2], c[mt][nt][3]);
            }
    } else {
        const float sc = 0.08838834764831845f * 1.4426950408889634f;  // rsqrt(128)*log2e
#pragma unroll
        for (int mt = 0; mt < 4; mt++)
#pragma unroll
            for (int nt = 0; nt < 4; nt++) {
                int row = bm + wm + mt * 16 + (lane >> 2);
                int col = bn + wn + nt * 8 + (lane & 3) * 2;
                float v0 = c[mt][nt][0], v1 = c[mt][nt][1];
                float v2 = c[mt][nt][2], v3 = c[mt][nt][3];
                if (bn < EMB) {           // q region, pre-scaled
                    *(uint32_t*)(q16 + (size_t)row * EMB + col) =
                        phf2(v0 * sc, v1 * sc);
                    *(uint32_t*)(q16 + (size_t)(row + 8) * EMB + col) =
                        phf2(v2 * sc, v3 * sc);
                } else if (bn < EMB + DH) {  // K region: split hi/lo
                    int lc = col - EMB;
                    __half h0 = __float2half_rn(v0), h1 = __float2half_rn(v1);
                    __half h2 = __float2half_rn(v2), h3 = __float2half_rn(v3);
                    *(uint32_t*)(khi + (size_t)row * DH + lc) =
                        (uint32_t)*(uint16_t*)&h0 | ((uint32_t)*(uint16_t*)&h1 << 16);
                    *(uint32_t*)(khi + (size_t)(row + 8) * DH + lc) =
                        (uint32_t)*(uint16_t*)&h2 | ((uint32_t)*(uint16_t*)&h3 << 16);
                    *(uint32_t*)(klo + (size_t)row * DH + lc) =
                        phf2(v0 - __half2float(h0), v1 - __half2float(h1));
                    *(uint32_t*)(klo + (size_t)(row + 8) * DH + lc) =
                        phf2(v2 - __half2float(h2), v3 - __half2float(h3));
                } else {                  // V region: single f16
                    int lc = col - EMB - DH;
                    *(uint32_t*)(v16 + (size_t)row * DH + lc) = phf2(v0, v1);
                    *(uint32_t*)(v16 + (size_t)(row + 8) * DH + lc) = phf2(v2, v3);
                }
            }
    }
}

// ---------------------------------------------------------------------------
// Tensor-core flash MQA: Q f16 (pre-scaled, cp.async) x K split-f16 (2-pass),
// P f16 x V f16 (1-pass), row-sum via ones-column. 3-stage K/V pipeline.
// ---------------------------------------------------------------------------
#define FROW    272
#define OFF_Q   0
#define OFF_ST  (128 * FROW)
#define STAGEF  (3 * 64 * FROW)         // Khi Klo V = 52224
#define FSMEM   (OFF_ST + 3 * STAGEF)   // 191488

__device__ __forceinline__ void issue_kv_tile(
    uint32_t stbase, int lr, int lcb, size_t ge,
    const __half* __restrict__ khi, const __half* __restrict__ klo,
    const __half* __restrict__ v16) {
    uint32_t d = stbase + (uint32_t)(lr * FROW + lcb);
    const char* pk = (const char*)(khi + ge);
    const char* pK = (const char*)(klo + ge);
    const char* pv = (const char*)(v16 + ge);
#pragma unroll
    for (int jj = 0; jj < 4; jj++) {
        cp_async16(d + jj * 16, pk + jj * 16);
        cp_async16(d + 64 * FROW + jj * 16, pK + jj * 16);
        cp_async16(d + 128 * FROW + jj * 16, pv + jj * 16);
    }
}

__global__ void __launch_bounds__(256, 1)
mqa_flash_mma(const __half* __restrict__ gq16,
              const __half* __restrict__ gkhi, const __half* __restrict__ gklo,
              const __half* __restrict__ gv16, __half* __restrict__ a16) {
    extern __shared__ char smf[];
    const uint32_t sb = smem_u32(smf);
    const int tid  = threadIdx.x;
    const int wid  = tid >> 5;
    const int lane = tid & 31;
    const int q0 = blockIdx.x * 128;
    const int h  = blockIdx.y;
    const int b  = blockIdx.z;
    const int wm = wid * 16;

    // ones column (V col 128) in all 3 stages, written once
    if (tid < 192) {
        int s = tid >> 6, row = tid & 63;
        char* vrow = smf + OFF_ST + s * STAGEF + 128 * FROW + row * FROW + 256;
        *(uint4*)vrow = make_uint4(0x00003C00u, 0u, 0u, 0u);
    }

    const int lr  = tid >> 2;
    const int lcb = (tid & 3) * 64;
    const size_t gebase = ((size_t)(b * SEQ + lr) << 7) + (lcb >> 1);

    // ---- prologue: Q tile (cp.async, pre-scaled f16) + KV tile 0, then KV 1 ----
    {
        int row = tid >> 1, c0 = (tid & 1) * 64;
        const char* src = (const char*)(gq16 + (size_t)(b * SEQ + q0 + row) * EMB +
                                        h * DH + c0);
        uint32_t dq = sb + OFF_Q + (uint32_t)(row * FROW + c0 * 2);
#pragma unroll
        for (int p = 0; p < 8; p++) cp_async16(dq + p * 16, src + p * 16);
    }
    issue_kv_tile(sb + OFF_ST, lr, lcb, gebase, gkhi, gklo, gv16);
    cp_commit();
    issue_kv_tile(sb + OFF_ST + STAGEF, lr, lcb, gebase + 64 * 128,
                  gkhi, gklo, gv16);
    cp_commit();

    float O[17][4];
#pragma unroll
    for (int f = 0; f < 17; f++)
#pragma unroll
        for (int j = 0; j < 4; j++) O[f][j] = 0.0f;
    float m0 = -1e30f, m1 = -1e30f;

    const int NT = SEQ / 64;
    int sidx = 0;
    for (int t = 0; t < NT; t++) {
        if (t + 1 < NT) cp_wait1(); else cp_wait0();
        __syncthreads();
        if (t + 2 < NT) {
            int s2 = sidx + 2; if (s2 >= 3) s2 -= 3;
            issue_kv_tile(sb + OFF_ST + s2 * STAGEF, lr, lcb,
                          gebase + (size_t)(t + 2) * 64 * 128, gkhi, gklo, gv16);
            cp_commit();
        }
        const uint32_t stb = sb + OFF_ST + sidx * STAGEF;

        // ---- QK^T: Q f16 x (Khi + Klo), 2 passes, log2 domain ----
        float c[8][4];
#pragma unroll
        for (int nt = 0; nt < 8; nt++)
#pragma unroll
            for (int j = 0; j < 4; j++) c[nt][j] = 0.0f;

#pragma unroll
        for (int ks = 0; ks < 8; ks++) {
            const uint32_t kcol = (uint32_t)(ks * 32 + (lane >> 4) * 16);
            uint32_t aq[4], kh[4][4], kl[4][4];
            ldsm4(aq, sb + OFF_Q + (uint32_t)((wm + (lane & 15)) * FROW) + kcol);
#pragma unroll
            for (int g = 0; g < 4; g++) {
                uint32_t ko = stb + (uint32_t)((g * 16 + (lane & 15)) * FROW) + kcol;
                ldsm4(kh[g], ko);
                ldsm4(kl[g], ko + 64 * FROW);
            }
#pragma unroll
            for (int g = 0; g < 4; g++) {
                mma_f16a(c[2 * g],     aq, kh[g][0], kh[g][2]);
                mma_f16a(c[2 * g + 1], aq, kh[g][1], kh[g][3]);
            }
#pragma unroll
            for (int g = 0; g < 4; g++) {
                mma_f16a(c[2 * g],     aq, kl[g][0], kl[g][2]);
                mma_f16a(c[2 * g + 1], aq, kl[g][1], kl[g][3]);
            }
        }

        // ---- online softmax (log2 domain), p in f16x2 ----
        float mt0 = -1e30f, mt1 = -1e30f;
#pragma unroll
        for (int nt = 0; nt < 8; nt++) {
            mt0 = fmaxf(mt0, fmaxf(c[nt][0], c[nt][1]));
            mt1 = fmaxf(mt1, fmaxf(c[nt][2], c[nt][3]));
        }
        mt0 = fmaxf(mt0, __shfl_xor_sync(0xffffffffu, mt0, 1));
        mt0 = fmaxf(mt0, __shfl_xor_sync(0xffffffffu, mt0, 2));
        mt1 = fmaxf(mt1, __shfl_xor_sync(0xffffffffu, mt1, 1));
        mt1 = fmaxf(mt1, __shfl_xor_sync(0xffffffffu, mt1, 2));
        float mn0 = fmaxf(m0, mt0), mn1 = fmaxf(m1, mt1);
        float corr0 = ex2f(m0 - mn0), corr1 = ex2f(m1 - mn1);
        m0 = mn0;
        m1 = mn1;
#pragma unroll
        for (int f = 0; f < 17; f++) {
            O[f][0] *= corr0; O[f][1] *= corr0;
            O[f][2] *= corr1; O[f][3] *= corr1;
        }
        uint32_t ph[8][2];
#pragma unroll
        for (int nt = 0; nt < 8; nt++) {
            ph[nt][0] = ex2_f16x2(c[nt][1] - mn0, c[nt][0] - mn0);
            ph[nt][1] = ex2_f16x2(c[nt][3] - mn1, c[nt][2] - mn1);
        }

        // ---- PV: P f16 x V f16; col 128 = row sum ----
        const uint32_t vb = stb + 128 * FROW;
#pragma unroll
        for (int j = 0; j < 4; j++) {
            uint32_t a0 = ph[2 * j][0], a1 = ph[2 * j][1];
            uint32_t a2 = ph[2 * j + 1][0], a3 = ph[2 * j + 1][1];
            uint32_t vrow = vb + (uint32_t)((j * 16 + (lane & 15)) * FROW);
            const uint32_t ccol = (uint32_t)((lane >> 4) * 8) * 2;
            uint32_t vfa[4][4];
#pragma unroll
            for (int g = 0; g < 4; g++) ldsm4t(vfa[g], vrow + g * 32 + ccol);
#pragma unroll
            for (int g = 0; g < 4; g++) {
                mma_f16(O[2 * g],     a0, a1, a2, a3, vfa[g][0], vfa[g][1]);
                mma_f16(O[2 * g + 1], a0, a1, a2, a3, vfa[g][2], vfa[g][3]);
            }
#pragma unroll
            for (int g = 0; g < 4; g++) ldsm4t(vfa[g], vrow + 128 + g * 32 + ccol);
#pragma unroll
            for (int g = 0; g < 4; g++) {
                mma_f16(O[8 + 2 * g],     a0, a1, a2, a3, vfa[g][0], vfa[g][1]);
                mma_f16(O[8 + 2 * g + 1], a0, a1, a2, a3, vfa[g][2], vfa[g][3]);
            }
            uint32_t lh[2];
            ldsm2t(lh, vrow + 256);
            mma_f16(O[16], a0, a1, a2, a3, lh[0], lh[1]);
        }
        sidx = (sidx + 1 == 3) ? 0 : sidx + 1;
    }

    // ---- epilogue: normalize, write f16 attn ----
    float l0 = __shfl_sync(0xffffffffu, O[16][0], lane & 28);
    float l1 = __shfl_sync(0xffffffffu, O[16][2], lane & 28);
    float inv0 = 1.0f / l0, inv1 = 1.0f / l1;
    size_t base0 = (size_t)(b * SEQ + q0 + wm + (lane >> 2)) * EMB + h * DH +
                   2 * (lane & 3);
    size_t base1 = base0 + (size_t)8 * EMB;
#pragma unroll
    for (int nt = 0; nt < 16; nt++) {
        *(uint32_t*)(a16 + base0 + nt * 8) = phf2(O[nt][0] * inv0, O[nt][1] * inv0);
        *(uint32_t*)(a16 + base1 + nt * 8) = phf2(O[nt][2] * inv1, O[nt][3] * inv1);
    }
}

// ---------------------------------------------------------------------------
extern "C" void kernel_launch(void* const* d_in, const int* in_sizes, int n_in,
                              void* d_out, int out_size) {
    const float* x      = (const float*)d_in[0];
    const float* w_attn = (const float*)d_in[1];
    const float* w_out  = (const float*)d_in[2];
    float* out = (float*)d_out;

    __half *x16, *wahi, *walo, *wohi, *wolo, *q16, *a16, *khi, *klo, *v16;
    cudaGetSymbolAddress((void**)&x16, g_x16);
    cudaGetSymbolAddress((void**)&wahi, g_wahi);
    cudaGetSymbolAddress((void**)&walo, g_walo);
    cudaGetSymbolAddress((void**)&wohi, g_wohi);
    cudaGetSymbolAddress((void**)&wolo, g_wolo);
    cudaGetSymbolAddress((void**)&q16, g_q16);
    cudaGetSymbolAddress((void**)&a16, g_a16);
    cudaGetSymbolAddress((void**)&khi, g_khi);
    cudaGetSymbolAddress((void**)&klo, g_klo);
    cudaGetSymbolAddress((void**)&v16, g_v16);

    cudaFuncSetAttribute(gemm_mma<0>, cudaFuncAttributeMaxDynamicSharedMemorySize,
                         GSMEM);
    cudaFuncSetAttribute(gemm_mma<1>, cudaFuncAttributeMaxDynamicSharedMemorySize,
                         GSMEM);
    cudaFuncSetAttribute(mqa_flash_mma, cudaFuncAttributeMaxDynamicSharedMemorySize,
                         FSMEM);

    // 1) convert inputs
    conv_f16<<<512, 256>>>(x, x16, MROWS * EMB / 4);
    transpose_split_f16<<<dim3(QKVN / 32, EMB / 32), 256>>>(w_attn, wahi, walo,
                                                            EMB, QKVN);
    transpose_split_f16<<<dim3(EMB / 32, EMB / 32), 256>>>(w_out, wohi, wolo,
                                                           EMB, EMB);

    // 2) qkv = x @ w_attn with fused q-scale/K-split/V epilogue
    gemm_mma<1><<<dim3(QKVN / 128, MROWS / 128), 256, GSMEM>>>(
        x16, wahi, walo, nullptr, q16, khi, klo, v16, QKVN);

    // 3) tensor-core flash MQA -> f16 attn
    mqa_flash_mma<<<dim3(SEQ / 128, NH, BSZ), 256, FSMEM>>>(
        q16, khi, klo, v16, a16);

    // 4) out = attn @ w_out
    gemm_mma<0><<<dim3(EMB / 128, MROWS / 128), 256, GSMEM>>>(
        a16, wohi, wolo, out, nullptr, nullptr, nullptr, nullptr, EMB);
}

// round 11
// speedup vs baseline: 1.7754x; 1.1686x over previous
#include <cuda_runtime.h>
#include <cuda_bf16.h>
#include <cuda_fp16.h>
#include <math.h>
#include <stdint.h>

#define BSZ   2
#define SEQ   2048
#define EMB   2048
#define NH    16
#define DH    128
#define QKVN  ((NH + 2) * DH)   // 2304
#define MROWS (BSZ * SEQ)       // 4096
#define GK    2048               // inner K of both GEMMs

// ---------------- scratch (__device__ globals: allocation-free) ------------
__device__ __align__(128) __half g_x16[(size_t)MROWS * EMB];
__device__ __align__(128) __half g_wahi[(size_t)QKVN * EMB];
__device__ __align__(128) __half g_walo[(size_t)QKVN * EMB];
__device__ __align__(128) __half g_wohi[(size_t)EMB * EMB];
__device__ __align__(128) __half g_wolo[(size_t)EMB * EMB];
__device__ __align__(128) __half g_q16[(size_t)MROWS * EMB];   // pre-scaled q
__device__ __align__(128) __half g_a16[(size_t)MROWS * EMB];
__device__ __align__(128) __half g_k16[(size_t)MROWS * DH];
__device__ __align__(128) __half g_v16[(size_t)MROWS * DH];

// ---------------- PTX helpers (sm_80-class only; no 'a' features) ----------
__device__ __forceinline__ uint32_t smem_u32(const void* p) {
    uint32_t a;
    asm("{ .reg .u64 t; cvta.to.shared.u64 t, %1; cvt.u32.u64 %0, t; }"
        : "=r"(a) : "l"(p));
    return a;
}
__device__ __forceinline__ void cp_async16(uint32_t dst, const void* src) {
    asm volatile("cp.async.cg.shared.global [%0], [%1], 16;"
                 :: "r"(dst), "l"(src) : "memory");
}
__device__ __forceinline__ void cp_commit() {
    asm volatile("cp.async.commit_group;" ::: "memory");
}
__device__ __forceinline__ void cp_wait1() {
    asm volatile("cp.async.wait_group 1;" ::: "memory");
}
__device__ __forceinline__ void cp_wait0() {
    asm volatile("cp.async.wait_group 0;" ::: "memory");
}
__device__ __forceinline__ void ldsm4(uint32_t* r, uint32_t addr) {
    asm volatile("ldmatrix.sync.aligned.m8n8.x4.shared.b16 {%0,%1,%2,%3}, [%4];"
                 : "=r"(r[0]), "=r"(r[1]), "=r"(r[2]), "=r"(r[3]) : "r"(addr));
}
__device__ __forceinline__ void ldsm4t(uint32_t* r, uint32_t addr) {
    asm volatile("ldmatrix.sync.aligned.m8n8.x4.trans.shared.b16 {%0,%1,%2,%3}, [%4];"
                 : "=r"(r[0]), "=r"(r[1]), "=r"(r[2]), "=r"(r[3]) : "r"(addr));
}
__device__ __forceinline__ void ldsm2t(uint32_t* r, uint32_t addr) {
    asm volatile("ldmatrix.sync.aligned.m8n8.x2.trans.shared.b16 {%0,%1}, [%2];"
                 : "=r"(r[0]), "=r"(r[1]) : "r"(addr));
}
__device__ __forceinline__ void mma_f16a(float* c, const uint32_t* a,
                                         uint32_t b0, uint32_t b1) {
    asm volatile(
        "mma.sync.aligned.m16n8k16.row.col.f32.f16.f16.f32 "
        "{%0,%1,%2,%3}, {%4,%5,%6,%7}, {%8,%9}, {%0,%1,%2,%3};"
        : "+f"(c[0]), "+f"(c[1]), "+f"(c[2]), "+f"(c[3])
        : "r"(a[0]), "r"(a[1]), "r"(a[2]), "r"(a[3]), "r"(b0), "r"(b1));
}
__device__ __forceinline__ void mma_f16(float* c, uint32_t a0, uint32_t a1,
                                        uint32_t a2, uint32_t a3,
                                        uint32_t b0, uint32_t b1) {
    asm volatile(
        "mma.sync.aligned.m16n8k16.row.col.f32.f16.f16.f32 "
        "{%0,%1,%2,%3}, {%4,%5,%6,%7}, {%8,%9}, {%0,%1,%2,%3};"
        : "+f"(c[0]), "+f"(c[1]), "+f"(c[2]), "+f"(c[3])
        : "r"(a0), "r"(a1), "r"(a2), "r"(a3), "r"(b0), "r"(b1));
}
__device__ __forceinline__ uint32_t ex2_f16x2(float xhi, float xlo) {
    uint32_t h, r;
    asm("cvt.rn.f16x2.f32 %0, %1, %2;" : "=r"(h) : "f"(xhi), "f"(xlo));
    asm("ex2.approx.f16x2 %0, %1;" : "=r"(r) : "r"(h));
    return r;
}
__device__ __forceinline__ float ex2f(float x) {
    float r;
    asm("ex2.approx.f32 %0, %1;" : "=f"(r) : "f"(x));
    return r;
}
__device__ __forceinline__ uint32_t phf2(float x, float y) {
    __half2 t(__float2half_rn(x), __float2half_rn(y));
    return *(uint32_t*)&t;
}

// ---------------------------------------------------------------------------
// fp32 -> f16 elementwise
// ---------------------------------------------------------------------------
__global__ void __launch_bounds__(256) conv_f16(const float* __restrict__ src,
                                                __half* __restrict__ dst, int n4) {
    int i = blockIdx.x * blockDim.x + threadIdx.x;
    int stride = gridDim.x * blockDim.x;
    for (; i < n4; i += stride) {
        float4 v = ((const float4*)src)[i];
        ((uint32_t*)dst)[2 * i]     = phf2(v.x, v.y);
        ((uint32_t*)dst)[2 * i + 1] = phf2(v.z, v.w);
    }
}

// ---------------------------------------------------------------------------
// transpose + split-f16: src [R][C] fp32 -> hi/lo [C][R] f16 (half2 stores)
// ---------------------------------------------------------------------------
__global__ void __launch_bounds__(256) transpose_split_f16(
    const float* __restrict__ src, __half* __restrict__ hi,
    __half* __restrict__ lo, int R, int C) {
    __shared__ float t[32][33];
    int c0 = blockIdx.x * 32, r0 = blockIdx.y * 32;
    int tx = threadIdx.x & 31, ty = threadIdx.x >> 5;
#pragma unroll
    for (int i = 0; i < 32; i += 8)
        t[ty + i][tx] = src[(size_t)(r0 + ty + i) * C + c0 + tx];
    __syncthreads();
    int tx2 = threadIdx.x & 15;   // r-pair index
    int ty2 = threadIdx.x >> 4;   // 0..15 (c rows)
#pragma unroll
    for (int i = 0; i < 32; i += 16) {
        int cc = ty2 + i;
        float v0 = t[2 * tx2][cc];
        float v1 = t[2 * tx2 + 1][cc];
        __half h0 = __float2half_rn(v0), h1 = __float2half_rn(v1);
        size_t o = (size_t)(c0 + cc) * R + r0 + 2 * tx2;
        *(uint32_t*)(hi + o) =
            (uint32_t)*(uint16_t*)&h0 | ((uint32_t)*(uint16_t*)&h1 << 16);
        *(uint32_t*)(lo + o) =
            phf2(v0 - __half2float(h0), v1 - __half2float(h1));
    }
}

// ---------------------------------------------------------------------------
// Asymmetric split-f16 GEMM, 2 mma passes, 3-stage cp.async pipeline.
// MODE 0: C = fp32 out.  MODE 1: fused qkv epilogue -> q16(scaled)/k16/v16.
// ---------------------------------------------------------------------------
#define KCH     32
#define ROWB    80
#define TILEB   (128 * ROWB)          // 10240
#define OFF_A   0
#define OFF_BHI TILEB
#define OFF_BLO (2 * TILEB)
#define STAGEB  (3 * TILEB)           // 30720
#define GSMEM   (3 * STAGEB)          // 92160

template <int MODE>
__global__ void __launch_bounds__(256)
gemm_mma(const __half* __restrict__ A, const __half* __restrict__ Bhi,
         const __half* __restrict__ Blo, float* __restrict__ C,
         __half* __restrict__ q16, __half* __restrict__ k16,
         __half* __restrict__ v16, int N) {
    extern __shared__ char smc[];
    const uint32_t sbase = smem_u32(smc);

    const int tid  = threadIdx.x;
    const int wid  = tid >> 5;
    const int lane = tid & 31;
    const int bm = blockIdx.y * 128;
    const int bn = blockIdx.x * 128;
    const int wm = (wid >> 2) * 64;
    const int wn = (wid & 3) * 32;

    const int r  = tid >> 1;
    const int hf = tid & 1;
    const __half* pA  = A   + (size_t)(bm + r) * GK + hf * 16;
    const __half* pBh = Bhi + (size_t)(bn + r) * GK + hf * 16;
    const __half* pBl = Blo + (size_t)(bn + r) * GK + hf * 16;
    const uint32_t dst = (uint32_t)(r * ROWB + hf * 32);

    float c[4][4][4];
#pragma unroll
    for (int mt = 0; mt < 4; mt++)
#pragma unroll
        for (int nt = 0; nt < 4; nt++)
#pragma unroll
            for (int k = 0; k < 4; k++) c[mt][nt][k] = 0.0f;

    const int NCH = GK / KCH;   // 64

    // prologue: chunks 0 and 1 -> stages 0 and 1
#pragma unroll
    for (int p = 0; p < 2; p++) {
        const uint32_t st = sbase + p * STAGEB;
        const int k0 = p * KCH;
        cp_async16(st + OFF_A + dst, pA + k0);
        cp_async16(st + OFF_A + dst + 16, pA + k0 + 8);
        cp_async16(st + OFF_BHI + dst, pBh + k0);
        cp_async16(st + OFF_BHI + dst + 16, pBh + k0 + 8);
        cp_async16(st + OFF_BLO + dst, pBl + k0);
        cp_async16(st + OFF_BLO + dst + 16, pBl + k0 + 8);
        cp_commit();
    }

    int sidx = 0;
    for (int ch = 0; ch < NCH; ch++) {
        if (ch + 1 < NCH) cp_wait1(); else cp_wait0();
        __syncthreads();
        if (ch + 2 < NCH) {
            int s2 = sidx + 2; if (s2 >= 3) s2 -= 3;
            const uint32_t st2 = sbase + s2 * STAGEB;
            const int k0 = (ch + 2) * KCH;
            cp_async16(st2 + OFF_A + dst, pA + k0);
            cp_async16(st2 + OFF_A + dst + 16, pA + k0 + 8);
            cp_async16(st2 + OFF_BHI + dst, pBh + k0);
            cp_async16(st2 + OFF_BHI + dst + 16, pBh + k0 + 8);
            cp_async16(st2 + OFF_BLO + dst, pBl + k0);
            cp_async16(st2 + OFF_BLO + dst + 16, pBl + k0 + 8);
            cp_commit();
        }
        const uint32_t st = sbase + sidx * STAGEB;

#pragma unroll
        for (int ks = 0; ks < 2; ks++) {
            const uint32_t kcol = (uint32_t)(ks * 32 + (lane >> 4) * 16);
            uint32_t a[4][4];
#pragma unroll
            for (int mt = 0; mt < 4; mt++) {
                uint32_t ra = st + OFF_A +
                              (uint32_t)((wm + mt * 16 + (lane & 15)) * ROWB) + kcol;
                ldsm4(a[mt], ra);
            }
            uint32_t rb0 = st + OFF_BHI +
                           (uint32_t)((wn + (lane & 15)) * ROWB) + kcol;
            uint32_t rb1 = rb0 + 16 * ROWB;
            uint32_t bh0[4], bh1[4], bl0[4], bl1[4];
            ldsm4(bh0, rb0);
            ldsm4(bh1, rb1);
            ldsm4(bl0, rb0 + TILEB);
            ldsm4(bl1, rb1 + TILEB);

#pragma unroll
            for (int mt = 0; mt < 4; mt++) {
                mma_f16a(c[mt][0], a[mt], bh0[0], bh0[2]);
                mma_f16a(c[mt][1], a[mt], bh0[1], bh0[3]);
                mma_f16a(c[mt][2], a[mt], bh1[0], bh1[2]);
                mma_f16a(c[mt][3], a[mt], bh1[1], bh1[3]);
            }
#pragma unroll
            for (int mt = 0; mt < 4; mt++) {
                mma_f16a(c[mt][0], a[mt], bl0[0], bl0[2]);
                mma_f16a(c[mt][1], a[mt], bl0[1], bl0[3]);
                mma_f16a(c[mt][2], a[mt], bl1[0], bl1[2]);
                mma_f16a(c[mt][3], a[mt], bl1[1], bl1[3]);
            }
        }
        sidx = (sidx + 1 == 3) ? 0 : sidx + 1;
    }

    // ---- epilogue ----
    if (MODE == 0) {
#pragma unroll
        for (int mt = 0; mt < 4; mt++)
#pragma unroll
            for (int nt = 0; nt < 4; nt++) {
                int row = bm + wm + mt * 16 + (lane >> 2);
                int col = bn + wn + nt * 8 + (lane & 3) * 2;
                *(float2*)&C[(size_t)row * N + col] =
                    make_float2(c[mt][nt][0], c[mt][nt][1]);
                *(float2*)&C[(size_t)(row + 8) * N + col] =
                    make_float2(c[mt][nt][2], c[mt][nt][3]);
            }
    } else {
        const float sc = 0.08838834764831845f * 1.4426950408889634f;  // rsqrt(128)*log2e
#pragma unroll
        for (int mt = 0; mt < 4; mt++)
#pragma unroll
            for (int nt = 0; nt < 4; nt++) {
                int row = bm + wm + mt * 16 + (lane >> 2);
                int col = bn + wn + nt * 8 + (lane & 3) * 2;
                float v0 = c[mt][nt][0], v1 = c[mt][nt][1];
                float v2 = c[mt][nt][2], v3 = c[mt][nt][3];
                if (bn < EMB) {           // q region, pre-scaled
                    *(uint32_t*)(q16 + (size_t)row * EMB + col) =
                        phf2(v0 * sc, v1 * sc);
                    *(uint32_t*)(q16 + (size_t)(row + 8) * EMB + col) =
                        phf2(v2 * sc, v3 * sc);
                } else if (bn < EMB + DH) {  // K region: single f16
                    int lc = col - EMB;
                    *(uint32_t*)(k16 + (size_t)row * DH + lc) = phf2(v0, v1);
                    *(uint32_t*)(k16 + (size_t)(row + 8) * DH + lc) = phf2(v2, v3);
                } else {                  // V region: single f16
                    int lc = col - EMB - DH;
                    *(uint32_t*)(v16 + (size_t)row * DH + lc) = phf2(v0, v1);
                    *(uint32_t*)(v16 + (size_t)(row + 8) * DH + lc) = phf2(v2, v3);
                }
            }
    }
}

// ---------------------------------------------------------------------------
// Tensor-core flash MQA: Q f16 (pre-scaled) x K f16 (1-pass QK),
// P f16 x V f16 (1-pass PV), row-sum via ones-column. 3-stage K/V pipeline.
// ---------------------------------------------------------------------------
#define FROW    272
#define OFF_Q   0
#define OFF_ST  (128 * FROW)
#define STAGEF  (2 * 64 * FROW)         // K16 + V16 = 34816
#define FSMEM   (OFF_ST + 3 * STAGEF)   // 139264

__device__ __forceinline__ void issue_kv_tile(
    uint32_t stbase, int lr, int lcb, size_t ge,
    const __half* __restrict__ k16, const __half* __restrict__ v16) {
    uint32_t d = stbase + (uint32_t)(lr * FROW + lcb);
    const char* pk = (const char*)(k16 + ge);
    const char* pv = (const char*)(v16 + ge);
#pragma unroll
    for (int jj = 0; jj < 4; jj++) {
        cp_async16(d + jj * 16, pk + jj * 16);
        cp_async16(d + 64 * FROW + jj * 16, pv + jj * 16);
    }
}

__global__ void __launch_bounds__(256, 1)
mqa_flash_mma(const __half* __restrict__ gq16,
              const __half* __restrict__ gk16,
              const __half* __restrict__ gv16, __half* __restrict__ a16) {
    extern __shared__ char smf[];
    const uint32_t sb = smem_u32(smf);
    const int tid  = threadIdx.x;
    const int wid  = tid >> 5;
    const int lane = tid & 31;
    const int q0 = blockIdx.x * 128;
    const int h  = blockIdx.y;
    const int b  = blockIdx.z;
    const int wm = wid * 16;

    // ones column (V col 128) in all 3 stages, written once
    if (tid < 192) {
        int s = tid >> 6, row = tid & 63;
        char* vrow = smf + OFF_ST + s * STAGEF + 64 * FROW + row * FROW + 256;
        *(uint4*)vrow = make_uint4(0x00003C00u, 0u, 0u, 0u);
    }

    const int lr  = tid >> 2;
    const int lcb = (tid & 3) * 64;
    const size_t gebase = ((size_t)(b * SEQ + lr) << 7) + (lcb >> 1);

    // ---- prologue: Q tile (cp.async) + KV tiles 0,1 ----
    {
        int row = tid >> 1, c0 = (tid & 1) * 64;
        const char* src = (const char*)(gq16 + (size_t)(b * SEQ + q0 + row) * EMB +
                                        h * DH + c0);
        uint32_t dq = sb + OFF_Q + (uint32_t)(row * FROW + c0 * 2);
#pragma unroll
        for (int p = 0; p < 8; p++) cp_async16(dq + p * 16, src + p * 16);
    }
    issue_kv_tile(sb + OFF_ST, lr, lcb, gebase, gk16, gv16);
    cp_commit();
    issue_kv_tile(sb + OFF_ST + STAGEF, lr, lcb, gebase + 64 * 128, gk16, gv16);
    cp_commit();

    float O[17][4];
#pragma unroll
    for (int f = 0; f < 17; f++)
#pragma unroll
        for (int j = 0; j < 4; j++) O[f][j] = 0.0f;
    float m0 = -1e30f, m1 = -1e30f;

    const int NT = SEQ / 64;
    int sidx = 0;
    for (int t = 0; t < NT; t++) {
        if (t + 1 < NT) cp_wait1(); else cp_wait0();
        __syncthreads();
        if (t + 2 < NT) {
            int s2 = sidx + 2; if (s2 >= 3) s2 -= 3;
            issue_kv_tile(sb + OFF_ST + s2 * STAGEF, lr, lcb,
                          gebase + (size_t)(t + 2) * 64 * 128, gk16, gv16);
            cp_commit();
        }
        const uint32_t stb = sb + OFF_ST + sidx * STAGEF;

        // ---- QK^T: Q f16 x K f16, 1 pass, log2 domain ----
        float c[8][4];
#pragma unroll
        for (int nt = 0; nt < 8; nt++)
#pragma unroll
            for (int j = 0; j < 4; j++) c[nt][j] = 0.0f;

#pragma unroll
        for (int ks = 0; ks < 8; ks++) {
            const uint32_t kcol = (uint32_t)(ks * 32 + (lane >> 4) * 16);
            uint32_t aq[4], kh[4][4];
            ldsm4(aq, sb + OFF_Q + (uint32_t)((wm + (lane & 15)) * FROW) + kcol);
#pragma unroll
            for (int g = 0; g < 4; g++) {
                uint32_t ko = stb + (uint32_t)((g * 16 + (lane & 15)) * FROW) + kcol;
                ldsm4(kh[g], ko);
            }
#pragma unroll
            for (int g = 0; g < 4; g++) {
                mma_f16a(c[2 * g],     aq, kh[g][0], kh[g][2]);
                mma_f16a(c[2 * g + 1], aq, kh[g][1], kh[g][3]);
            }
        }

        // ---- online softmax (log2 domain), p in f16x2 ----
        float mt0 = -1e30f, mt1 = -1e30f;
#pragma unroll
        for (int nt = 0; nt < 8; nt++) {
            mt0 = fmaxf(mt0, fmaxf(c[nt][0], c[nt][1]));
            mt1 = fmaxf(mt1, fmaxf(c[nt][2], c[nt][3]));
        }
        mt0 = fmaxf(mt0, __shfl_xor_sync(0xffffffffu, mt0, 1));
        mt0 = fmaxf(mt0, __shfl_xor_sync(0xffffffffu, mt0, 2));
        mt1 = fmaxf(mt1, __shfl_xor_sync(0xffffffffu, mt1, 1));
        mt1 = fmaxf(mt1, __shfl_xor_sync(0xffffffffu, mt1, 2));
        float mn0 = fmaxf(m0, mt0), mn1 = fmaxf(m1, mt1);
        float corr0 = ex2f(m0 - mn0), corr1 = ex2f(m1 - mn1);
        m0 = mn0;
        m1 = mn1;
#pragma unroll
        for (int f = 0; f < 17; f++) {
            O[f][0] *= corr0; O[f][1] *= corr0;
            O[f][2] *= corr1; O[f][3] *= corr1;
        }
        uint32_t ph[8][2];
#pragma unroll
        for (int nt = 0; nt < 8; nt++) {
            ph[nt][0] = ex2_f16x2(c[nt][1] - mn0, c[nt][0] - mn0);
            ph[nt][1] = ex2_f16x2(c[nt][3] - mn1, c[nt][2] - mn1);
        }

        // ---- PV: P f16 x V f16; col 128 = row sum ----
        const uint32_t vb = stb + 64 * FROW;
#pragma unroll
        for (int j = 0; j < 4; j++) {
            uint32_t a0 = ph[2 * j][0], a1 = ph[2 * j][1];
            uint32_t a2 = ph[2 * j + 1][0], a3 = ph[2 * j + 1][1];
            uint32_t vrow = vb + (uint32_t)((j * 16 + (lane & 15)) * FROW);
            const uint32_t ccol = (uint32_t)((lane >> 4) * 8) * 2;
            uint32_t vfa[4][4];
#pragma unroll
            for (int g = 0; g < 4; g++) ldsm4t(vfa[g], vrow + g * 32 + ccol);
#pragma unroll
            for (int g = 0; g < 4; g++) {
                mma_f16(O[2 * g],     a0, a1, a2, a3, vfa[g][0], vfa[g][1]);
                mma_f16(O[2 * g + 1], a0, a1, a2, a3, vfa[g][2], vfa[g][3]);
            }
#pragma unroll
            for (int g = 0; g < 4; g++) ldsm4t(vfa[g], vrow + 128 + g * 32 + ccol);
#pragma unroll
            for (int g = 0; g < 4; g++) {
                mma_f16(O[8 + 2 * g],     a0, a1, a2, a3, vfa[g][0], vfa[g][1]);
                mma_f16(O[8 + 2 * g + 1], a0, a1, a2, a3, vfa[g][2], vfa[g][3]);
            }
            uint32_t lh[2];
            ldsm2t(lh, vrow + 256);
            mma_f16(O[16], a0, a1, a2, a3, lh[0], lh[1]);
        }
        sidx = (sidx + 1 == 3) ? 0 : sidx + 1;
    }

    // ---- epilogue: normalize, write f16 attn ----
    float l0 = __shfl_sync(0xffffffffu, O[16][0], lane & 28);
    float l1 = __shfl_sync(0xffffffffu, O[16][2], lane & 28);
    float inv0 = 1.0f / l0, inv1 = 1.0f / l1;
    size_t base0 = (size_t)(b * SEQ + q0 + wm + (lane >> 2)) * EMB + h * DH +
                   2 * (lane & 3);
    size_t base1 = base0 + (size_t)8 * EMB;
#pragma unroll
    for (int nt = 0; nt < 16; nt++) {
        *(uint32_t*)(a16 + base0 + nt * 8) = phf2(O[nt][0] * inv0, O[nt][1] * inv0);
        *(uint32_t*)(a16 + base1 + nt * 8) = phf2(O[nt][2] * inv1, O[nt][3] * inv1);
    }
}

// ---------------------------------------------------------------------------
extern "C" void kernel_launch(void* const* d_in, const int* in_sizes, int n_in,
                              void* d_out, int out_size) {
    const float* x      = (const float*)d_in[0];
    const float* w_attn = (const float*)d_in[1];
    const float* w_out  = (const float*)d_in[2];
    float* out = (float*)d_out;

    __half *x16, *wahi, *walo, *wohi, *wolo, *q16, *a16, *k16, *v16;
    cudaGetSymbolAddress((void**)&x16, g_x16);
    cudaGetSymbolAddress((void**)&wahi, g_wahi);
    cudaGetSymbolAddress((void**)&walo, g_walo);
    cudaGetSymbolAddress((void**)&wohi, g_wohi);
    cudaGetSymbolAddress((void**)&wolo, g_wolo);
    cudaGetSymbolAddress((void**)&q16, g_q16);
    cudaGetSymbolAddress((void**)&a16, g_a16);
    cudaGetSymbolAddress((void**)&k16, g_k16);
    cudaGetSymbolAddress((void**)&v16, g_v16);

    cudaFuncSetAttribute(gemm_mma<0>, cudaFuncAttributeMaxDynamicSharedMemorySize,
                         GSMEM);
    cudaFuncSetAttribute(gemm_mma<1>, cudaFuncAttributeMaxDynamicSharedMemorySize,
                         GSMEM);
    cudaFuncSetAttribute(mqa_flash_mma, cudaFuncAttributeMaxDynamicSharedMemorySize,
                         FSMEM);

    // 1) convert inputs
    conv_f16<<<512, 256>>>(x, x16, MROWS * EMB / 4);
    transpose_split_f16<<<dim3(QKVN / 32, EMB / 32), 256>>>(w_attn, wahi, walo,
                                                            EMB, QKVN);
    transpose_split_f16<<<dim3(EMB / 32, EMB / 32), 256>>>(w_out, wohi, wolo,
                                                           EMB, EMB);

    // 2) qkv = x @ w_attn with fused q-scale/k16/v16 epilogue
    gemm_mma<1><<<dim3(QKVN / 128, MROWS / 128), 256, GSMEM>>>(
        x16, wahi, walo, nullptr, q16, k16, v16, QKVN);

    // 3) tensor-core flash MQA -> f16 attn
    mqa_flash_mma<<<dim3(SEQ / 128, NH, BSZ), 256, FSMEM>>>(
        q16, k16, v16, a16);

    // 4) out = attn @ w_out
    gemm_mma<0><<<dim3(EMB / 128, MROWS / 128), 256, GSMEM>>>(
        a16, wohi, wolo, out, nullptr, nullptr, nullptr, EMB);
}

// round 12
// speedup vs baseline: 2.3415x; 1.3188x over previous
#include <cuda_runtime.h>
#include <cuda_bf16.h>
#include <cuda_fp16.h>
#include <math.h>
#include <stdint.h>

#define BSZ   2
#define SEQ   2048
#define EMB   2048
#define NH    16
#define DH    128
#define QKVN  ((NH + 2) * DH)   // 2304
#define MROWS (BSZ * SEQ)       // 4096
#define GK    2048               // inner K of both GEMMs

// ---------------- scratch (__device__ globals: allocation-free) ------------
__device__ __align__(128) __half g_x16[(size_t)MROWS * EMB];
__device__ __align__(128) __half g_wa16[(size_t)QKVN * EMB];
__device__ __align__(128) __half g_wo16[(size_t)EMB * EMB];
__device__ __align__(128) __half g_q16[(size_t)MROWS * EMB];   // pre-scaled q
__device__ __align__(128) __half g_a16[(size_t)MROWS * EMB];
__device__ __align__(128) __half g_k16[(size_t)MROWS * DH];
__device__ __align__(128) __half g_v16[(size_t)MROWS * DH];

// ---------------- PTX helpers (sm_80-class only; no 'a' features) ----------
__device__ __forceinline__ uint32_t smem_u32(const void* p) {
    uint32_t a;
    asm("{ .reg .u64 t; cvta.to.shared.u64 t, %1; cvt.u32.u64 %0, t; }"
        : "=r"(a) : "l"(p));
    return a;
}
__device__ __forceinline__ void cp_async16(uint32_t dst, const void* src) {
    asm volatile("cp.async.cg.shared.global [%0], [%1], 16;"
                 :: "r"(dst), "l"(src) : "memory");
}
__device__ __forceinline__ void cp_commit() {
    asm volatile("cp.async.commit_group;" ::: "memory");
}
__device__ __forceinline__ void cp_wait1() {
    asm volatile("cp.async.wait_group 1;" ::: "memory");
}
__device__ __forceinline__ void cp_wait0() {
    asm volatile("cp.async.wait_group 0;" ::: "memory");
}
__device__ __forceinline__ void ldsm4(uint32_t* r, uint32_t addr) {
    asm volatile("ldmatrix.sync.aligned.m8n8.x4.shared.b16 {%0,%1,%2,%3}, [%4];"
                 : "=r"(r[0]), "=r"(r[1]), "=r"(r[2]), "=r"(r[3]) : "r"(addr));
}
__device__ __forceinline__ void ldsm4t(uint32_t* r, uint32_t addr) {
    asm volatile("ldmatrix.sync.aligned.m8n8.x4.trans.shared.b16 {%0,%1,%2,%3}, [%4];"
                 : "=r"(r[0]), "=r"(r[1]), "=r"(r[2]), "=r"(r[3]) : "r"(addr));
}
__device__ __forceinline__ void ldsm2t(uint32_t* r, uint32_t addr) {
    asm volatile("ldmatrix.sync.aligned.m8n8.x2.trans.shared.b16 {%0,%1}, [%2];"
                 : "=r"(r[0]), "=r"(r[1]) : "r"(addr));
}
__device__ __forceinline__ void mma_f16a(float* c, const uint32_t* a,
                                         uint32_t b0, uint32_t b1) {
    asm volatile(
        "mma.sync.aligned.m16n8k16.row.col.f32.f16.f16.f32 "
        "{%0,%1,%2,%3}, {%4,%5,%6,%7}, {%8,%9}, {%0,%1,%2,%3};"
        : "+f"(c[0]), "+f"(c[1]), "+f"(c[2]), "+f"(c[3])
        : "r"(a[0]), "r"(a[1]), "r"(a[2]), "r"(a[3]), "r"(b0), "r"(b1));
}
__device__ __forceinline__ void mma_f16(float* c, uint32_t a0, uint32_t a1,
                                        uint32_t a2, uint32_t a3,
                                        uint32_t b0, uint32_t b1) {
    asm volatile(
        "mma.sync.aligned.m16n8k16.row.col.f32.f16.f16.f32 "
        "{%0,%1,%2,%3}, {%4,%5,%6,%7}, {%8,%9}, {%0,%1,%2,%3};"
        : "+f"(c[0]), "+f"(c[1]), "+f"(c[2]), "+f"(c[3])
        : "r"(a0), "r"(a1), "r"(a2), "r"(a3), "r"(b0), "r"(b1));
}
__device__ __forceinline__ uint32_t ex2_f16x2(float xhi, float xlo) {
    uint32_t h, r;
    asm("cvt.rn.f16x2.f32 %0, %1, %2;" : "=r"(h) : "f"(xhi), "f"(xlo));
    asm("ex2.approx.f16x2 %0, %1;" : "=r"(r) : "r"(h));
    return r;
}
__device__ __forceinline__ float ex2f(float x) {
    float r;
    asm("ex2.approx.f32 %0, %1;" : "=f"(r) : "f"(x));
    return r;
}
__device__ __forceinline__ uint32_t phf2(float x, float y) {
    __half2 t(__float2half_rn(x), __float2half_rn(y));
    return *(uint32_t*)&t;
}

// ---------------------------------------------------------------------------
// fp32 -> f16 elementwise
// ---------------------------------------------------------------------------
__global__ void __launch_bounds__(256) conv_f16(const float* __restrict__ src,
                                                __half* __restrict__ dst, int n4) {
    int i = blockIdx.x * blockDim.x + threadIdx.x;
    int stride = gridDim.x * blockDim.x;
    for (; i < n4; i += stride) {
        float4 v = ((const float4*)src)[i];
        ((uint32_t*)dst)[2 * i]     = phf2(v.x, v.y);
        ((uint32_t*)dst)[2 * i + 1] = phf2(v.z, v.w);
    }
}

// ---------------------------------------------------------------------------
// transpose to f16: src [R][C] fp32 -> dst [C][R] f16 (half2 stores)
// ---------------------------------------------------------------------------
__global__ void __launch_bounds__(256) transpose_f16(
    const float* __restrict__ src, __half* __restrict__ dst, int R, int C) {
    __shared__ float t[32][33];
    int c0 = blockIdx.x * 32, r0 = blockIdx.y * 32;
    int tx = threadIdx.x & 31, ty = threadIdx.x >> 5;
#pragma unroll
    for (int i = 0; i < 32; i += 8)
        t[ty + i][tx] = src[(size_t)(r0 + ty + i) * C + c0 + tx];
    __syncthreads();
    int tx2 = threadIdx.x & 15;
    int ty2 = threadIdx.x >> 4;
#pragma unroll
    for (int i = 0; i < 32; i += 16) {
        int cc = ty2 + i;
        size_t o = (size_t)(c0 + cc) * R + r0 + 2 * tx2;
        *(uint32_t*)(dst + o) = phf2(t[2 * tx2][cc], t[2 * tx2 + 1][cc]);
    }
}

// ---------------------------------------------------------------------------
// Plain f16 GEMM via mma.sync: C[M,N] = A16 @ B16^T  (single pass)
// CTA 128x128, 8 warps x (64x32), K chunk 32, 3-stage cp.async (offset 2).
// MODE 0: fp32 C out.  MODE 1: fused qkv epilogue -> q16(scaled)/k16/v16.
// ---------------------------------------------------------------------------
#define KCH     32
#define ROWB    80
#define TILEB   (128 * ROWB)          // 10240
#define OFF_A   0
#define OFF_B   TILEB
#define STAGEB  (2 * TILEB)           // 20480
#define GSMEM   (3 * STAGEB)          // 61440

template <int MODE>
__global__ void __launch_bounds__(256)
gemm_mma(const __half* __restrict__ A, const __half* __restrict__ B,
         float* __restrict__ C, __half* __restrict__ q16,
         __half* __restrict__ k16, __half* __restrict__ v16, int N) {
    extern __shared__ char smc[];
    const uint32_t sbase = smem_u32(smc);

    const int tid  = threadIdx.x;
    const int wid  = tid >> 5;
    const int lane = tid & 31;
    const int bm = blockIdx.y * 128;
    const int bn = blockIdx.x * 128;
    const int wm = (wid >> 2) * 64;
    const int wn = (wid & 3) * 32;

    const int r  = tid >> 1;
    const int hf = tid & 1;
    const __half* pA = A + (size_t)(bm + r) * GK + hf * 16;
    const __half* pB = B + (size_t)(bn + r) * GK + hf * 16;
    const uint32_t dst = (uint32_t)(r * ROWB + hf * 32);

    float c[4][4][4];
#pragma unroll
    for (int mt = 0; mt < 4; mt++)
#pragma unroll
        for (int nt = 0; nt < 4; nt++)
#pragma unroll
            for (int k = 0; k < 4; k++) c[mt][nt][k] = 0.0f;

    const int NCH = GK / KCH;   // 64

    // prologue: chunks 0,1 -> stages 0,1
#pragma unroll
    for (int p = 0; p < 2; p++) {
        const uint32_t st = sbase + p * STAGEB;
        const int k0 = p * KCH;
        cp_async16(st + OFF_A + dst, pA + k0);
        cp_async16(st + OFF_A + dst + 16, pA + k0 + 8);
        cp_async16(st + OFF_B + dst, pB + k0);
        cp_async16(st + OFF_B + dst + 16, pB + k0 + 8);
        cp_commit();
    }

    int sidx = 0;
    for (int ch = 0; ch < NCH; ch++) {
        if (ch + 1 < NCH) cp_wait1(); else cp_wait0();
        __syncthreads();
        if (ch + 2 < NCH) {
            int s2 = sidx + 2; if (s2 >= 3) s2 -= 3;
            const uint32_t st2 = sbase + s2 * STAGEB;
            const int k0 = (ch + 2) * KCH;
            cp_async16(st2 + OFF_A + dst, pA + k0);
            cp_async16(st2 + OFF_A + dst + 16, pA + k0 + 8);
            cp_async16(st2 + OFF_B + dst, pB + k0);
            cp_async16(st2 + OFF_B + dst + 16, pB + k0 + 8);
            cp_commit();
        }
        const uint32_t st = sbase + sidx * STAGEB;

#pragma unroll
        for (int ks = 0; ks < 2; ks++) {
            const uint32_t kcol = (uint32_t)(ks * 32 + (lane >> 4) * 16);
            uint32_t a[4][4];
#pragma unroll
            for (int mt = 0; mt < 4; mt++) {
                uint32_t ra = st + OFF_A +
                              (uint32_t)((wm + mt * 16 + (lane & 15)) * ROWB) + kcol;
                ldsm4(a[mt], ra);
            }
            uint32_t rb0 = st + OFF_B +
                           (uint32_t)((wn + (lane & 15)) * ROWB) + kcol;
            uint32_t rb1 = rb0 + 16 * ROWB;
            uint32_t bh0[4], bh1[4];
            ldsm4(bh0, rb0);
            ldsm4(bh1, rb1);

#pragma unroll
            for (int mt = 0; mt < 4; mt++) {
                mma_f16a(c[mt][0], a[mt], bh0[0], bh0[2]);
                mma_f16a(c[mt][1], a[mt], bh0[1], bh0[3]);
                mma_f16a(c[mt][2], a[mt], bh1[0], bh1[2]);
                mma_f16a(c[mt][3], a[mt], bh1[1], bh1[3]);
            }
        }
        sidx = (sidx + 1 == 3) ? 0 : sidx + 1;
    }

    // ---- epilogue ----
    if (MODE == 0) {
#pragma unroll
        for (int mt = 0; mt < 4; mt++)
#pragma unroll
            for (int nt = 0; nt < 4; nt++) {
                int row = bm + wm + mt * 16 + (lane >> 2);
                int col = bn + wn + nt * 8 + (lane & 3) * 2;
                *(float2*)&C[(size_t)row * N + col] =
                    make_float2(c[mt][nt][0], c[mt][nt][1]);
                *(float2*)&C[(size_t)(row + 8) * N + col] =
                    make_float2(c[mt][nt][2], c[mt][nt][3]);
            }
    } else {
        const float sc = 0.08838834764831845f * 1.4426950408889634f;  // rsqrt(128)*log2e
#pragma unroll
        for (int mt = 0; mt < 4; mt++)
#pragma unroll
            for (int nt = 0; nt < 4; nt++) {
                int row = bm + wm + mt * 16 + (lane >> 2);
                int col = bn + wn + nt * 8 + (lane & 3) * 2;
                float v0 = c[mt][nt][0], v1 = c[mt][nt][1];
                float v2 = c[mt][nt][2], v3 = c[mt][nt][3];
                if (bn < EMB) {           // q region, pre-scaled
                    *(uint32_t*)(q16 + (size_t)row * EMB + col) =
                        phf2(v0 * sc, v1 * sc);
                    *(uint32_t*)(q16 + (size_t)(row + 8) * EMB + col) =
                        phf2(v2 * sc, v3 * sc);
                } else if (bn < EMB + DH) {  // K region
                    int lc = col - EMB;
                    *(uint32_t*)(k16 + (size_t)row * DH + lc) = phf2(v0, v1);
                    *(uint32_t*)(k16 + (size_t)(row + 8) * DH + lc) = phf2(v2, v3);
                } else {                  // V region
                    int lc = col - EMB - DH;
                    *(uint32_t*)(v16 + (size_t)row * DH + lc) = phf2(v0, v1);
                    *(uint32_t*)(v16 + (size_t)(row + 8) * DH + lc) = phf2(v2, v3);
                }
            }
    }
}

// ---------------------------------------------------------------------------
// Tensor-core flash MQA: Q f16 (pre-scaled) x K f16, P f16 x V f16,
// row-sum via ones-column. 3-stage K/V cp.async pipeline.
// ---------------------------------------------------------------------------
#define FROW    272
#define OFF_Q   0
#define OFF_ST  (128 * FROW)
#define STAGEF  (2 * 64 * FROW)         // K16 + V16 = 34816
#define FSMEM   (OFF_ST + 3 * STAGEF)   // 139264

__device__ __forceinline__ void issue_kv_tile(
    uint32_t stbase, int lr, int lcb, size_t ge,
    const __half* __restrict__ k16, const __half* __restrict__ v16) {
    uint32_t d = stbase + (uint32_t)(lr * FROW + lcb);
    const char* pk = (const char*)(k16 + ge);
    const char* pv = (const char*)(v16 + ge);
#pragma unroll
    for (int jj = 0; jj < 4; jj++) {
        cp_async16(d + jj * 16, pk + jj * 16);
        cp_async16(d + 64 * FROW + jj * 16, pv + jj * 16);
    }
}

__global__ void __launch_bounds__(256, 1)
mqa_flash_mma(const __half* __restrict__ gq16,
              const __half* __restrict__ gk16,
              const __half* __restrict__ gv16, __half* __restrict__ a16) {
    extern __shared__ char smf[];
    const uint32_t sb = smem_u32(smf);
    const int tid  = threadIdx.x;
    const int wid  = tid >> 5;
    const int lane = tid & 31;
    const int q0 = blockIdx.x * 128;
    const int h  = blockIdx.y;
    const int b  = blockIdx.z;
    const int wm = wid * 16;

    // ones column (V col 128) in all 3 stages, written once
    if (tid < 192) {
        int s = tid >> 6, row = tid & 63;
        char* vrow = smf + OFF_ST + s * STAGEF + 64 * FROW + row * FROW + 256;
        *(uint4*)vrow = make_uint4(0x00003C00u, 0u, 0u, 0u);
    }

    const int lr  = tid >> 2;
    const int lcb = (tid & 3) * 64;
    const size_t gebase = ((size_t)(b * SEQ + lr) << 7) + (lcb >> 1);

    // ---- prologue: Q tile (cp.async) + KV tiles 0,1 ----
    {
        int row = tid >> 1, c0 = (tid & 1) * 64;
        const char* src = (const char*)(gq16 + (size_t)(b * SEQ + q0 + row) * EMB +
                                        h * DH + c0);
        uint32_t dq = sb + OFF_Q + (uint32_t)(row * FROW + c0 * 2);
#pragma unroll
        for (int p = 0; p < 8; p++) cp_async16(dq + p * 16, src + p * 16);
    }
    issue_kv_tile(sb + OFF_ST, lr, lcb, gebase, gk16, gv16);
    cp_commit();
    issue_kv_tile(sb + OFF_ST + STAGEF, lr, lcb, gebase + 64 * 128, gk16, gv16);
    cp_commit();

    float O[17][4];
#pragma unroll
    for (int f = 0; f < 17; f++)
#pragma unroll
        for (int j = 0; j < 4; j++) O[f][j] = 0.0f;
    float m0 = -1e30f, m1 = -1e30f;

    const int NT = SEQ / 64;
    int sidx = 0;
    for (int t = 0; t < NT; t++) {
        if (t + 1 < NT) cp_wait1(); else cp_wait0();
        __syncthreads();
        if (t + 2 < NT) {
            int s2 = sidx + 2; if (s2 >= 3) s2 -= 3;
            issue_kv_tile(sb + OFF_ST + s2 * STAGEF, lr, lcb,
                          gebase + (size_t)(t + 2) * 64 * 128, gk16, gv16);
            cp_commit();
        }
        const uint32_t stb = sb + OFF_ST + sidx * STAGEF;

        // ---- QK^T: Q f16 x K f16, log2 domain ----
        float c[8][4];
#pragma unroll
        for (int nt = 0; nt < 8; nt++)
#pragma unroll
            for (int j = 0; j < 4; j++) c[nt][j] = 0.0f;

#pragma unroll
        for (int ks = 0; ks < 8; ks++) {
            const uint32_t kcol = (uint32_t)(ks * 32 + (lane >> 4) * 16);
            uint32_t aq[4], kh[4][4];
            ldsm4(aq, sb + OFF_Q + (uint32_t)((wm + (lane & 15)) * FROW) + kcol);
#pragma unroll
            for (int g = 0; g < 4; g++) {
                uint32_t ko = stb + (uint32_t)((g * 16 + (lane & 15)) * FROW) + kcol;
                ldsm4(kh[g], ko);
            }
#pragma unroll
            for (int g = 0; g < 4; g++) {
                mma_f16a(c[2 * g],     aq, kh[g][0], kh[g][2]);
                mma_f16a(c[2 * g + 1], aq, kh[g][1], kh[g][3]);
            }
        }

        // ---- online softmax (log2 domain), p in f16x2 ----
        float mt0 = -1e30f, mt1 = -1e30f;
#pragma unroll
        for (int nt = 0; nt < 8; nt++) {
            mt0 = fmaxf(mt0, fmaxf(c[nt][0], c[nt][1]));
            mt1 = fmaxf(mt1, fmaxf(c[nt][2], c[nt][3]));
        }
        mt0 = fmaxf(mt0, __shfl_xor_sync(0xffffffffu, mt0, 1));
        mt0 = fmaxf(mt0, __shfl_xor_sync(0xffffffffu, mt0, 2));
        mt1 = fmaxf(mt1, __shfl_xor_sync(0xffffffffu, mt1, 1));
        mt1 = fmaxf(mt1, __shfl_xor_sync(0xffffffffu, mt1, 2));
        float mn0 = fmaxf(m0, mt0), mn1 = fmaxf(m1, mt1);
        float corr0 = ex2f(m0 - mn0), corr1 = ex2f(m1 - mn1);
        m0 = mn0;
        m1 = mn1;
#pragma unroll
        for (int f = 0; f < 17; f++) {
            O[f][0] *= corr0; O[f][1] *= corr0;
            O[f][2] *= corr1; O[f][3] *= corr1;
        }
        uint32_t ph[8][2];
#pragma unroll
        for (int nt = 0; nt < 8; nt++) {
            ph[nt][0] = ex2_f16x2(c[nt][1] - mn0, c[nt][0] - mn0);
            ph[nt][1] = ex2_f16x2(c[nt][3] - mn1, c[nt][2] - mn1);
        }

        // ---- PV: P f16 x V f16; col 128 = row sum ----
        const uint32_t vb = stb + 64 * FROW;
#pragma unroll
        for (int j = 0; j < 4; j++) {
            uint32_t a0 = ph[2 * j][0], a1 = ph[2 * j][1];
            uint32_t a2 = ph[2 * j + 1][0], a3 = ph[2 * j + 1][1];
            uint32_t vrow = vb + (uint32_t)((j * 16 + (lane & 15)) * FROW);
            const uint32_t ccol = (uint32_t)((lane >> 4) * 8) * 2;
            uint32_t vfa[4][4];
#pragma unroll
            for (int g = 0; g < 4; g++) ldsm4t(vfa[g], vrow + g * 32 + ccol);
#pragma unroll
            for (int g = 0; g < 4; g++) {
                mma_f16(O[2 * g],     a0, a1, a2, a3, vfa[g][0], vfa[g][1]);
                mma_f16(O[2 * g + 1], a0, a1, a2, a3, vfa[g][2], vfa[g][3]);
            }
#pragma unroll
            for (int g = 0; g < 4; g++) ldsm4t(vfa[g], vrow + 128 + g * 32 + ccol);
#pragma unroll
            for (int g = 0; g < 4; g++) {
                mma_f16(O[8 + 2 * g],     a0, a1, a2, a3, vfa[g][0], vfa[g][1]);
                mma_f16(O[8 + 2 * g + 1], a0, a1, a2, a3, vfa[g][2], vfa[g][3]);
            }
            uint32_t lh[2];
            ldsm2t(lh, vrow + 256);
            mma_f16(O[16], a0, a1, a2, a3, lh[0], lh[1]);
        }
        sidx = (sidx + 1 == 3) ? 0 : sidx + 1;
    }

    // ---- epilogue: normalize, write f16 attn ----
    float l0 = __shfl_sync(0xffffffffu, O[16][0], lane & 28);
    float l1 = __shfl_sync(0xffffffffu, O[16][2], lane & 28);
    float inv0 = 1.0f / l0, inv1 = 1.0f / l1;
    size_t base0 = (size_t)(b * SEQ + q0 + wm + (lane >> 2)) * EMB + h * DH +
                   2 * (lane & 3);
    size_t base1 = base0 + (size_t)8 * EMB;
#pragma unroll
    for (int nt = 0; nt < 16; nt++) {
        *(uint32_t*)(a16 + base0 + nt * 8) = phf2(O[nt][0] * inv0, O[nt][1] * inv0);
        *(uint32_t*)(a16 + base1 + nt * 8) = phf2(O[nt][2] * inv1, O[nt][3] * inv1);
    }
}

// ---------------------------------------------------------------------------
extern "C" void kernel_launch(void* const* d_in, const int* in_sizes, int n_in,
                              void* d_out, int out_size) {
    const float* x      = (const float*)d_in[0];
    const float* w_attn = (const float*)d_in[1];
    const float* w_out  = (const float*)d_in[2];
    float* out = (float*)d_out;

    __half *x16, *wa16, *wo16, *q16, *a16, *k16, *v16;
    cudaGetSymbolAddress((void**)&x16, g_x16);
    cudaGetSymbolAddress((void**)&wa16, g_wa16);
    cudaGetSymbolAddress((void**)&wo16, g_wo16);
    cudaGetSymbolAddress((void**)&q16, g_q16);
    cudaGetSymbolAddress((void**)&a16, g_a16);
    cudaGetSymbolAddress((void**)&k16, g_k16);
    cudaGetSymbolAddress((void**)&v16, g_v16);

    cudaFuncSetAttribute(gemm_mma<0>, cudaFuncAttributeMaxDynamicSharedMemorySize,
                         GSMEM);
    cudaFuncSetAttribute(gemm_mma<1>, cudaFuncAttributeMaxDynamicSharedMemorySize,
                         GSMEM);
    cudaFuncSetAttribute(mqa_flash_mma, cudaFuncAttributeMaxDynamicSharedMemorySize,
                         FSMEM);

    // 1) convert inputs
    conv_f16<<<512, 256>>>(x, x16, MROWS * EMB / 4);
    transpose_f16<<<dim3(QKVN / 32, EMB / 32), 256>>>(w_attn, wa16, EMB, QKVN);
    transpose_f16<<<dim3(EMB / 32, EMB / 32), 256>>>(w_out, wo16, EMB, EMB);

    // 2) qkv = x @ w_attn with fused q-scale/k16/v16 epilogue (single-pass f16)
    gemm_mma<1><<<dim3(QKVN / 128, MROWS / 128), 256, GSMEM>>>(
        x16, wa16, nullptr, q16, k16, v16, QKVN);

    // 3) tensor-core flash MQA -> f16 attn
    mqa_flash_mma<<<dim3(SEQ / 128, NH, BSZ), 256, FSMEM>>>(
        q16, k16, v16, a16);

    // 4) out = attn @ w_out (single-pass f16)
    gemm_mma<0><<<dim3(EMB / 128, MROWS / 128), 256, GSMEM>>>(
        a16, wo16, out, nullptr, nullptr, nullptr, EMB);
}

// round 13
// speedup vs baseline: 2.4033x; 1.0264x over previous
#include <cuda_runtime.h>
#include <cuda_bf16.h>
#include <cuda_fp16.h>
#include <math.h>
#include <stdint.h>

#define BSZ   2
#define SEQ   2048
#define EMB   2048
#define NH    16
#define DH    128
#define QKVN  ((NH + 2) * DH)   // 2304
#define MROWS (BSZ * SEQ)       // 4096
#define GK    2048               // inner K of both GEMMs

// ---------------- scratch (__device__ globals: allocation-free) ------------
__device__ __align__(128) __half g_x16[(size_t)MROWS * EMB];
__device__ __align__(128) __half g_wa16[(size_t)QKVN * EMB];
__device__ __align__(128) __half g_wo16[(size_t)EMB * EMB];
__device__ __align__(128) __half g_q16[(size_t)MROWS * EMB];   // pre-scaled q
__device__ __align__(128) __half g_a16[(size_t)MROWS * EMB];
__device__ __align__(128) __half g_k16[(size_t)MROWS * DH];
__device__ __align__(128) __half g_v16[(size_t)MROWS * DH];

// ---------------- PTX helpers (sm_80-class only; no 'a' features) ----------
__device__ __forceinline__ uint32_t smem_u32(const void* p) {
    uint32_t a;
    asm("{ .reg .u64 t; cvta.to.shared.u64 t, %1; cvt.u32.u64 %0, t; }"
        : "=r"(a) : "l"(p));
    return a;
}
__device__ __forceinline__ void cp_async16(uint32_t dst, const void* src) {
    asm volatile("cp.async.cg.shared.global [%0], [%1], 16;"
                 :: "r"(dst), "l"(src) : "memory");
}
__device__ __forceinline__ void cp_commit() {
    asm volatile("cp.async.commit_group;" ::: "memory");
}
__device__ __forceinline__ void cp_wait1() {
    asm volatile("cp.async.wait_group 1;" ::: "memory");
}
__device__ __forceinline__ void cp_wait0() {
    asm volatile("cp.async.wait_group 0;" ::: "memory");
}
__device__ __forceinline__ void ldsm4(uint32_t* r, uint32_t addr) {
    asm volatile("ldmatrix.sync.aligned.m8n8.x4.shared.b16 {%0,%1,%2,%3}, [%4];"
                 : "=r"(r[0]), "=r"(r[1]), "=r"(r[2]), "=r"(r[3]) : "r"(addr));
}
__device__ __forceinline__ void ldsm4t(uint32_t* r, uint32_t addr) {
    asm volatile("ldmatrix.sync.aligned.m8n8.x4.trans.shared.b16 {%0,%1,%2,%3}, [%4];"
                 : "=r"(r[0]), "=r"(r[1]), "=r"(r[2]), "=r"(r[3]) : "r"(addr));
}
__device__ __forceinline__ void ldsm2t(uint32_t* r, uint32_t addr) {
    asm volatile("ldmatrix.sync.aligned.m8n8.x2.trans.shared.b16 {%0,%1}, [%2];"
                 : "=r"(r[0]), "=r"(r[1]) : "r"(addr));
}
__device__ __forceinline__ void mma_f16a(float* c, const uint32_t* a,
                                         uint32_t b0, uint32_t b1) {
    asm volatile(
        "mma.sync.aligned.m16n8k16.row.col.f32.f16.f16.f32 "
        "{%0,%1,%2,%3}, {%4,%5,%6,%7}, {%8,%9}, {%0,%1,%2,%3};"
        : "+f"(c[0]), "+f"(c[1]), "+f"(c[2]), "+f"(c[3])
        : "r"(a[0]), "r"(a[1]), "r"(a[2]), "r"(a[3]), "r"(b0), "r"(b1));
}
__device__ __forceinline__ void mma_f16(float* c, uint32_t a0, uint32_t a1,
                                        uint32_t a2, uint32_t a3,
                                        uint32_t b0, uint32_t b1) {
    asm volatile(
        "mma.sync.aligned.m16n8k16.row.col.f32.f16.f16.f32 "
        "{%0,%1,%2,%3}, {%4,%5,%6,%7}, {%8,%9}, {%0,%1,%2,%3};"
        : "+f"(c[0]), "+f"(c[1]), "+f"(c[2]), "+f"(c[3])
        : "r"(a0), "r"(a1), "r"(a2), "r"(a3), "r"(b0), "r"(b1));
}
__device__ __forceinline__ uint32_t ex2_f16x2(float xhi, float xlo) {
    uint32_t h, r;
    asm("cvt.rn.f16x2.f32 %0, %1, %2;" : "=r"(h) : "f"(xhi), "f"(xlo));
    asm("ex2.approx.f16x2 %0, %1;" : "=r"(r) : "r"(h));
    return r;
}
__device__ __forceinline__ float ex2f(float x) {
    float r;
    asm("ex2.approx.f32 %0, %1;" : "=f"(r) : "f"(x));
    return r;
}
__device__ __forceinline__ uint32_t phf2(float x, float y) {
    __half2 t(__float2half_rn(x), __float2half_rn(y));
    return *(uint32_t*)&t;
}

// ---------------------------------------------------------------------------
// fp32 -> f16 elementwise
// ---------------------------------------------------------------------------
__global__ void __launch_bounds__(256) conv_f16(const float* __restrict__ src,
                                                __half* __restrict__ dst, int n4) {
    int i = blockIdx.x * blockDim.x + threadIdx.x;
    int stride = gridDim.x * blockDim.x;
    for (; i < n4; i += stride) {
        float4 v = ((const float4*)src)[i];
        ((uint32_t*)dst)[2 * i]     = phf2(v.x, v.y);
        ((uint32_t*)dst)[2 * i + 1] = phf2(v.z, v.w);
    }
}

// ---------------------------------------------------------------------------
// transpose to f16: src [R][C] fp32 -> dst [C][R] f16 (half2 stores)
// ---------------------------------------------------------------------------
__global__ void __launch_bounds__(256) transpose_f16(
    const float* __restrict__ src, __half* __restrict__ dst, int R, int C) {
    __shared__ float t[32][33];
    int c0 = blockIdx.x * 32, r0 = blockIdx.y * 32;
    int tx = threadIdx.x & 31, ty = threadIdx.x >> 5;
#pragma unroll
    for (int i = 0; i < 32; i += 8)
        t[ty + i][tx] = src[(size_t)(r0 + ty + i) * C + c0 + tx];
    __syncthreads();
    int tx2 = threadIdx.x & 15;
    int ty2 = threadIdx.x >> 4;
#pragma unroll
    for (int i = 0; i < 32; i += 16) {
        int cc = ty2 + i;
        size_t o = (size_t)(c0 + cc) * R + r0 + 2 * tx2;
        *(uint32_t*)(dst + o) = phf2(t[2 * tx2][cc], t[2 * tx2 + 1][cc]);
    }
}

// ---------------------------------------------------------------------------
// Plain f16 GEMM via mma.sync: C[M,N] = A16 @ B16^T  (single pass)
// CTA 128x128, 8 warps x (64x32), K chunk 32, 3-stage cp.async (offset 2).
// MODE 0: fp32 C out.  MODE 1: fused qkv epilogue -> q16(scaled)/k16/v16.
// ---------------------------------------------------------------------------
#define KCH     32
#define ROWB    80
#define TILEB   (128 * ROWB)          // 10240
#define OFF_A   0
#define OFF_B   TILEB
#define STAGEB  (2 * TILEB)           // 20480
#define GSMEM   (3 * STAGEB)          // 61440

template <int MODE>
__global__ void __launch_bounds__(256)
gemm_mma(const __half* __restrict__ A, const __half* __restrict__ B,
         float* __restrict__ C, __half* __restrict__ q16,
         __half* __restrict__ k16, __half* __restrict__ v16, int N) {
    extern __shared__ char smc[];
    const uint32_t sbase = smem_u32(smc);

    const int tid  = threadIdx.x;
    const int wid  = tid >> 5;
    const int lane = tid & 31;
    const int bm = blockIdx.y * 128;
    const int bn = blockIdx.x * 128;
    const int wm = (wid >> 2) * 64;
    const int wn = (wid & 3) * 32;

    const int r  = tid >> 1;
    const int hf = tid & 1;
    const __half* pA = A + (size_t)(bm + r) * GK + hf * 16;
    const __half* pB = B + (size_t)(bn + r) * GK + hf * 16;
    const uint32_t dst = (uint32_t)(r * ROWB + hf * 32);

    float c[4][4][4];
#pragma unroll
    for (int mt = 0; mt < 4; mt++)
#pragma unroll
        for (int nt = 0; nt < 4; nt++)
#pragma unroll
            for (int k = 0; k < 4; k++) c[mt][nt][k] = 0.0f;

    const int NCH = GK / KCH;   // 64

#pragma unroll
    for (int p = 0; p < 2; p++) {
        const uint32_t st = sbase + p * STAGEB;
        const int k0 = p * KCH;
        cp_async16(st + OFF_A + dst, pA + k0);
        cp_async16(st + OFF_A + dst + 16, pA + k0 + 8);
        cp_async16(st + OFF_B + dst, pB + k0);
        cp_async16(st + OFF_B + dst + 16, pB + k0 + 8);
        cp_commit();
    }

    int sidx = 0;
    for (int ch = 0; ch < NCH; ch++) {
        if (ch + 1 < NCH) cp_wait1(); else cp_wait0();
        __syncthreads();
        if (ch + 2 < NCH) {
            int s2 = sidx + 2; if (s2 >= 3) s2 -= 3;
            const uint32_t st2 = sbase + s2 * STAGEB;
            const int k0 = (ch + 2) * KCH;
            cp_async16(st2 + OFF_A + dst, pA + k0);
            cp_async16(st2 + OFF_A + dst + 16, pA + k0 + 8);
            cp_async16(st2 + OFF_B + dst, pB + k0);
            cp_async16(st2 + OFF_B + dst + 16, pB + k0 + 8);
            cp_commit();
        }
        const uint32_t st = sbase + sidx * STAGEB;

#pragma unroll
        for (int ks = 0; ks < 2; ks++) {
            const uint32_t kcol = (uint32_t)(ks * 32 + (lane >> 4) * 16);
            uint32_t a[4][4];
#pragma unroll
            for (int mt = 0; mt < 4; mt++) {
                uint32_t ra = st + OFF_A +
                              (uint32_t)((wm + mt * 16 + (lane & 15)) * ROWB) + kcol;
                ldsm4(a[mt], ra);
            }
            uint32_t rb0 = st + OFF_B +
                           (uint32_t)((wn + (lane & 15)) * ROWB) + kcol;
            uint32_t rb1 = rb0 + 16 * ROWB;
            uint32_t bh0[4], bh1[4];
            ldsm4(bh0, rb0);
            ldsm4(bh1, rb1);

#pragma unroll
            for (int mt = 0; mt < 4; mt++) {
                mma_f16a(c[mt][0], a[mt], bh0[0], bh0[2]);
                mma_f16a(c[mt][1], a[mt], bh0[1], bh0[3]);
                mma_f16a(c[mt][2], a[mt], bh1[0], bh1[2]);
                mma_f16a(c[mt][3], a[mt], bh1[1], bh1[3]);
            }
        }
        sidx = (sidx + 1 == 3) ? 0 : sidx + 1;
    }

    // ---- epilogue ----
    if (MODE == 0) {
#pragma unroll
        for (int mt = 0; mt < 4; mt++)
#pragma unroll
            for (int nt = 0; nt < 4; nt++) {
                int row = bm + wm + mt * 16 + (lane >> 2);
                int col = bn + wn + nt * 8 + (lane & 3) * 2;
                *(float2*)&C[(size_t)row * N + col] =
                    make_float2(c[mt][nt][0], c[mt][nt][1]);
                *(float2*)&C[(size_t)(row + 8) * N + col] =
                    make_float2(c[mt][nt][2], c[mt][nt][3]);
            }
    } else {
        const float sc = 0.08838834764831845f * 1.4426950408889634f;
#pragma unroll
        for (int mt = 0; mt < 4; mt++)
#pragma unroll
            for (int nt = 0; nt < 4; nt++) {
                int row = bm + wm + mt * 16 + (lane >> 2);
                int col = bn + wn + nt * 8 + (lane & 3) * 2;
                float v0 = c[mt][nt][0], v1 = c[mt][nt][1];
                float v2 = c[mt][nt][2], v3 = c[mt][nt][3];
                if (bn < EMB) {
                    *(uint32_t*)(q16 + (size_t)row * EMB + col) =
                        phf2(v0 * sc, v1 * sc);
                    *(uint32_t*)(q16 + (size_t)(row + 8) * EMB + col) =
                        phf2(v2 * sc, v3 * sc);
                } else if (bn < EMB + DH) {
                    int lc = col - EMB;
                    *(uint32_t*)(k16 + (size_t)row * DH + lc) = phf2(v0, v1);
                    *(uint32_t*)(k16 + (size_t)(row + 8) * DH + lc) = phf2(v2, v3);
                } else {
                    int lc = col - EMB - DH;
                    *(uint32_t*)(v16 + (size_t)row * DH + lc) = phf2(v0, v1);
                    *(uint32_t*)(v16 + (size_t)(row + 8) * DH + lc) = phf2(v2, v3);
                }
            }
    }
}

// ---------------------------------------------------------------------------
// Tensor-core flash MQA: Q f16 (pre-scaled) x K f16, P f16 x V f16,
// row-sum via ones-column. 2-stage K/V pipeline, 2 CTAs/SM.
// ---------------------------------------------------------------------------
#define FROW    272
#define OFF_Q   0
#define OFF_ST  (128 * FROW)
#define STAGEF  (2 * 64 * FROW)         // K16 + V16 = 34816
#define FSMEM   (OFF_ST + 2 * STAGEF)   // 104448 (2 CTAs/SM)

__device__ __forceinline__ void issue_kv_tile(
    uint32_t stbase, int lr, int lcb, size_t ge,
    const __half* __restrict__ k16, const __half* __restrict__ v16) {
    uint32_t d = stbase + (uint32_t)(lr * FROW + lcb);
    const char* pk = (const char*)(k16 + ge);
    const char* pv = (const char*)(v16 + ge);
#pragma unroll
    for (int jj = 0; jj < 4; jj++) {
        cp_async16(d + jj * 16, pk + jj * 16);
        cp_async16(d + 64 * FROW + jj * 16, pv + jj * 16);
    }
}

__global__ void __launch_bounds__(256, 2)
mqa_flash_mma(const __half* __restrict__ gq16,
              const __half* __restrict__ gk16,
              const __half* __restrict__ gv16, __half* __restrict__ a16) {
    extern __shared__ char smf[];
    const uint32_t sb = smem_u32(smf);
    const int tid  = threadIdx.x;
    const int wid  = tid >> 5;
    const int lane = tid & 31;
    const int q0 = blockIdx.x * 128;
    const int h  = blockIdx.y;
    const int b  = blockIdx.z;
    const int wm = wid * 16;

    // ones column (V col 128) in both stages, written once
    if (tid < 128) {
        int s = tid >> 6, row = tid & 63;
        char* vrow = smf + OFF_ST + s * STAGEF + 64 * FROW + row * FROW + 256;
        *(uint4*)vrow = make_uint4(0x00003C00u, 0u, 0u, 0u);
    }

    const int lr  = tid >> 2;
    const int lcb = (tid & 3) * 64;
    const size_t gebase = ((size_t)(b * SEQ + lr) << 7) + (lcb >> 1);

    // ---- prologue: Q tile (cp.async) + KV tiles 0,1 ----
    {
        int row = tid >> 1, c0 = (tid & 1) * 64;
        const char* src = (const char*)(gq16 + (size_t)(b * SEQ + q0 + row) * EMB +
                                        h * DH + c0);
        uint32_t dq = sb + OFF_Q + (uint32_t)(row * FROW + c0 * 2);
#pragma unroll
        for (int p = 0; p < 8; p++) cp_async16(dq + p * 16, src + p * 16);
    }
    issue_kv_tile(sb + OFF_ST, lr, lcb, gebase, gk16, gv16);
    cp_commit();
    issue_kv_tile(sb + OFF_ST + STAGEF, lr, lcb, gebase + 64 * 128, gk16, gv16);
    cp_commit();

    float O[17][4];
#pragma unroll
    for (int f = 0; f < 17; f++)
#pragma unroll
        for (int j = 0; j < 4; j++) O[f][j] = 0.0f;
    float m0 = -1e30f, m1 = -1e30f;

    const int NT = SEQ / 64;
    for (int t = 0; t < NT; t++) {
        if (t + 1 < NT) cp_wait1(); else cp_wait0();
        __syncthreads();
        const uint32_t stb = sb + OFF_ST + (t & 1) * STAGEF;

        // ---- QK^T: Q f16 x K f16, log2 domain ----
        float c[8][4];
#pragma unroll
        for (int nt = 0; nt < 8; nt++)
#pragma unroll
            for (int j = 0; j < 4; j++) c[nt][j] = 0.0f;

#pragma unroll
        for (int ks = 0; ks < 8; ks++) {
            const uint32_t kcol = (uint32_t)(ks * 32 + (lane >> 4) * 16);
            uint32_t aq[4], kh[4][4];
            ldsm4(aq, sb + OFF_Q + (uint32_t)((wm + (lane & 15)) * FROW) + kcol);
#pragma unroll
            for (int g = 0; g < 4; g++) {
                uint32_t ko = stb + (uint32_t)((g * 16 + (lane & 15)) * FROW) + kcol;
                ldsm4(kh[g], ko);
            }
#pragma unroll
            for (int g = 0; g < 4; g++) {
                mma_f16a(c[2 * g],     aq, kh[g][0], kh[g][2]);
                mma_f16a(c[2 * g + 1], aq, kh[g][1], kh[g][3]);
            }
        }

        // ---- online softmax (log2 domain), p in f16x2 ----
        float mt0 = -1e30f, mt1 = -1e30f;
#pragma unroll
        for (int nt = 0; nt < 8; nt++) {
            mt0 = fmaxf(mt0, fmaxf(c[nt][0], c[nt][1]));
            mt1 = fmaxf(mt1, fmaxf(c[nt][2], c[nt][3]));
        }
        mt0 = fmaxf(mt0, __shfl_xor_sync(0xffffffffu, mt0, 1));
        mt0 = fmaxf(mt0, __shfl_xor_sync(0xffffffffu, mt0, 2));
        mt1 = fmaxf(mt1, __shfl_xor_sync(0xffffffffu, mt1, 1));
        mt1 = fmaxf(mt1, __shfl_xor_sync(0xffffffffu, mt1, 2));
        float mn0 = fmaxf(m0, mt0), mn1 = fmaxf(m1, mt1);
        float corr0 = ex2f(m0 - mn0), corr1 = ex2f(m1 - mn1);
        m0 = mn0;
        m1 = mn1;
#pragma unroll
        for (int f = 0; f < 17; f++) {
            O[f][0] *= corr0; O[f][1] *= corr0;
            O[f][2] *= corr1; O[f][3] *= corr1;
        }
        uint32_t ph[8][2];
#pragma unroll
        for (int nt = 0; nt < 8; nt++) {
            ph[nt][0] = ex2_f16x2(c[nt][1] - mn0, c[nt][0] - mn0);
            ph[nt][1] = ex2_f16x2(c[nt][3] - mn1, c[nt][2] - mn1);
        }

        // ---- PV: P f16 x V f16; col 128 = row sum ----
        const uint32_t vb = stb + 64 * FROW;
#pragma unroll
        for (int j = 0; j < 4; j++) {
            uint32_t a0 = ph[2 * j][0], a1 = ph[2 * j][1];
            uint32_t a2 = ph[2 * j + 1][0], a3 = ph[2 * j + 1][1];
            uint32_t vrow = vb + (uint32_t)((j * 16 + (lane & 15)) * FROW);
            const uint32_t ccol = (uint32_t)((lane >> 4) * 8) * 2;
            uint32_t vfa[4][4];
#pragma unroll
            for (int g = 0; g < 4; g++) ldsm4t(vfa[g], vrow + g * 32 + ccol);
#pragma unroll
            for (int g = 0; g < 4; g++) {
                mma_f16(O[2 * g],     a0, a1, a2, a3, vfa[g][0], vfa[g][1]);
                mma_f16(O[2 * g + 1], a0, a1, a2, a3, vfa[g][2], vfa[g][3]);
            }
#pragma unroll
            for (int g = 0; g < 4; g++) ldsm4t(vfa[g], vrow + 128 + g * 32 + ccol);
#pragma unroll
            for (int g = 0; g < 4; g++) {
                mma_f16(O[8 + 2 * g],     a0, a1, a2, a3, vfa[g][0], vfa[g][1]);
                mma_f16(O[8 + 2 * g + 1], a0, a1, a2, a3, vfa[g][2], vfa[g][3]);
            }
            uint32_t lh[2];
            ldsm2t(lh, vrow + 256);
            mma_f16(O[16], a0, a1, a2, a3, lh[0], lh[1]);
        }

        // stage (t&1) fully consumed; refill with tile t+2
        __syncthreads();
        if (t + 2 < NT) {
            issue_kv_tile(stb, lr, lcb, gebase + (size_t)(t + 2) * 64 * 128,
                          gk16, gv16);
            cp_commit();
        }
    }

    // ---- epilogue: normalize, write f16 attn ----
    float l0 = __shfl_sync(0xffffffffu, O[16][0], lane & 28);
    float l1 = __shfl_sync(0xffffffffu, O[16][2], lane & 28);
    float inv0 = 1.0f / l0, inv1 = 1.0f / l1;
    size_t base0 = (size_t)(b * SEQ + q0 + wm + (lane >> 2)) * EMB + h * DH +
                   2 * (lane & 3);
    size_t base1 = base0 + (size_t)8 * EMB;
#pragma unroll
    for (int nt = 0; nt < 16; nt++) {
        *(uint32_t*)(a16 + base0 + nt * 8) = phf2(O[nt][0] * inv0, O[nt][1] * inv0);
        *(uint32_t*)(a16 + base1 + nt * 8) = phf2(O[nt][2] * inv1, O[nt][3] * inv1);
    }
}

// ---------------------------------------------------------------------------
extern "C" void kernel_launch(void* const* d_in, const int* in_sizes, int n_in,
                              void* d_out, int out_size) {
    const float* x      = (const float*)d_in[0];
    const float* w_attn = (const float*)d_in[1];
    const float* w_out  = (const float*)d_in[2];
    float* out = (float*)d_out;

    __half *x16, *wa16, *wo16, *q16, *a16, *k16, *v16;
    cudaGetSymbolAddress((void**)&x16, g_x16);
    cudaGetSymbolAddress((void**)&wa16, g_wa16);
    cudaGetSymbolAddress((void**)&wo16, g_wo16);
    cudaGetSymbolAddress((void**)&q16, g_q16);
    cudaGetSymbolAddress((void**)&a16, g_a16);
    cudaGetSymbolAddress((void**)&k16, g_k16);
    cudaGetSymbolAddress((void**)&v16, g_v16);

    cudaFuncSetAttribute(gemm_mma<0>, cudaFuncAttributeMaxDynamicSharedMemorySize,
                         GSMEM);
    cudaFuncSetAttribute(gemm_mma<1>, cudaFuncAttributeMaxDynamicSharedMemorySize,
                         GSMEM);
    cudaFuncSetAttribute(mqa_flash_mma, cudaFuncAttributeMaxDynamicSharedMemorySize,
                         FSMEM);

    // 1) convert inputs
    conv_f16<<<512, 256>>>(x, x16, MROWS * EMB / 4);
    transpose_f16<<<dim3(QKVN / 32, EMB / 32), 256>>>(w_attn, wa16, EMB, QKVN);
    transpose_f16<<<dim3(EMB / 32, EMB / 32), 256>>>(w_out, wo16, EMB, EMB);

    // 2) qkv = x @ w_attn with fused q-scale/k16/v16 epilogue
    gemm_mma<1><<<dim3(QKVN / 128, MROWS / 128), 256, GSMEM>>>(
        x16, wa16, nullptr, q16, k16, v16, QKVN);

    // 3) tensor-core flash MQA -> f16 attn (2 CTAs/SM)
    mqa_flash_mma<<<dim3(SEQ / 128, NH, BSZ), 256, FSMEM>>>(
        q16, k16, v16, a16);

    // 4) out = attn @ w_out
    gemm_mma<0><<<dim3(EMB / 128, MROWS / 128), 256, GSMEM>>>(
        a16, wo16, out, nullptr, nullptr, nullptr, EMB);
}